// round 1
// baseline (speedup 1.0000x reference)
#include <cuda_runtime.h>
#include <math.h>

// ---------------- problem constants ----------------
#define BATCH  2
#define SEQ    2048
#define EMB    256
#define DMODEL 512
#define NLAYER 4
#define DIN    1024
#define DSTATE 64
#define DRANK  32
#define DCONV  4
#define NCLS   5
#define XPN    (DRANK + 2*DSTATE)   // 160
#define MROWS  (BATCH*SEQ)          // 4096

// ---------------- scratch (static device globals; no allocation) ----------------
__device__ float g_xe  [MROWS*EMB];
__device__ float g_x   [MROWS*DMODEL];
__device__ float g_h   [MROWS*DMODEL];
__device__ float g_xr  [MROWS*2*DIN];
__device__ float g_xs  [MROWS*DIN];
__device__ float g_xdbl[MROWS*XPN];
__device__ float g_dlt [MROWS*DIN];
__device__ float g_y   [MROWS*DIN];
__device__ float g_hd1 [MROWS*256];
__device__ float g_hd2 [MROWS*128];

// ---------------- generic fp32 GEMM: C[M,N] = A[M,K] @ W[N,K]^T (+epilogue) ----------------
#define GBM 128
#define GBN 128
#define GBK 8
#define GTM 8
#define GTN 8

enum { EPI_NONE=0, EPI_BIAS=1, EPI_BIAS_RELU=2, EPI_BIAS_SOFTPLUS=3, EPI_RES=4 };

__global__ __launch_bounds__(256)
void sgemm_kernel(const float* __restrict__ A, int lda,
                  const float* __restrict__ Bw,           // [N,K], row-major
                  float* __restrict__ C, int ldc,
                  int M, int N, int K,
                  const float* __restrict__ bias,
                  const float* __restrict__ res,
                  int mode)
{
    __shared__ float As[GBK][GBM];
    __shared__ float Bs[GBK][GBN];
    const int tid  = threadIdx.x;
    const int bm   = blockIdx.y * GBM;
    const int bn   = blockIdx.x * GBN;
    const int tm   = (tid / 16) * GTM;
    const int tn   = (tid % 16) * GTN;
    const int lrow = tid >> 1;          // 0..127
    const int lk   = (tid & 1) * 4;     // 0 or 4

    float acc[GTM][GTN];
    #pragma unroll
    for (int i = 0; i < GTM; i++)
        #pragma unroll
        for (int j = 0; j < GTN; j++) acc[i][j] = 0.f;

    for (int k0 = 0; k0 < K; k0 += GBK) {
        float4 av = make_float4(0.f,0.f,0.f,0.f);
        float4 bv = make_float4(0.f,0.f,0.f,0.f);
        const int ar = bm + lrow;
        if (ar < M) av = *(const float4*)(A + (size_t)ar*lda + k0 + lk);
        const int br = bn + lrow;
        if (br < N) bv = *(const float4*)(Bw + (size_t)br*K + k0 + lk);
        As[lk+0][lrow]=av.x; As[lk+1][lrow]=av.y; As[lk+2][lrow]=av.z; As[lk+3][lrow]=av.w;
        Bs[lk+0][lrow]=bv.x; Bs[lk+1][lrow]=bv.y; Bs[lk+2][lrow]=bv.z; Bs[lk+3][lrow]=bv.w;
        __syncthreads();
        #pragma unroll
        for (int k = 0; k < GBK; k++) {
            float ra[GTM], rb[GTN];
            #pragma unroll
            for (int i = 0; i < GTM; i++) ra[i] = As[k][tm+i];
            #pragma unroll
            for (int j = 0; j < GTN; j++) rb[j] = Bs[k][tn+j];
            #pragma unroll
            for (int i = 0; i < GTM; i++)
                #pragma unroll
                for (int j = 0; j < GTN; j++)
                    acc[i][j] = fmaf(ra[i], rb[j], acc[i][j]);
        }
        __syncthreads();
    }

    #pragma unroll
    for (int i = 0; i < GTM; i++) {
        const int m = bm + tm + i;
        if (m >= M) continue;
        #pragma unroll
        for (int j = 0; j < GTN; j++) {
            const int n = bn + tn + j;
            if (n >= N) continue;
            float v = acc[i][j];
            if (mode == EPI_BIAS)            v += bias[n];
            else if (mode == EPI_BIAS_RELU)  { v += bias[n]; v = fmaxf(v, 0.f); }
            else if (mode == EPI_BIAS_SOFTPLUS) {
                v += bias[n];
                v = (v > 20.f) ? v : log1pf(expf(v));
            }
            else if (mode == EPI_RES)        v += res[(size_t)m*ldc + n];
            C[(size_t)m*ldc + n] = v;
        }
    }
}

// ---------------- embedding: x = byte_embed[seq] + pos_embed ----------------
__global__ void embed_kernel(const int* __restrict__ seq,
                             const float* __restrict__ be,
                             const float* __restrict__ pe,
                             float* __restrict__ xe)
{
    const int idx = blockIdx.x * blockDim.x + threadIdx.x;  // MROWS*EMB
    const int e   = idx & (EMB-1);
    const int row = idx >> 8;
    const int t   = row & (SEQ-1);
    const int by  = seq[row];
    xe[idx] = be[by*EMB + e] + pe[t*EMB + e];
}

// ---------------- layernorm over D=512 ----------------
__global__ void ln_kernel(const float* __restrict__ x,
                          const float* __restrict__ g,
                          const float* __restrict__ b,
                          float* __restrict__ out)
{
    const int row = blockIdx.x;
    const int tid = threadIdx.x;     // 128
    const float4 v = ((const float4*)(x + (size_t)row*DMODEL))[tid];
    float s  = v.x + v.y + v.z + v.w;
    float ss = v.x*v.x + v.y*v.y + v.z*v.z + v.w*v.w;
    #pragma unroll
    for (int o = 16; o; o >>= 1) {
        s  += __shfl_xor_sync(0xffffffffu, s,  o);
        ss += __shfl_xor_sync(0xffffffffu, ss, o);
    }
    __shared__ float sh_s[4], sh_ss[4];
    const int wid = tid >> 5, lane = tid & 31;
    if (lane == 0) { sh_s[wid] = s; sh_ss[wid] = ss; }
    __syncthreads();
    s  = sh_s[0] + sh_s[1] + sh_s[2] + sh_s[3];
    ss = sh_ss[0] + sh_ss[1] + sh_ss[2] + sh_ss[3];
    const float mu  = s * (1.f/DMODEL);
    const float inv = rsqrtf(ss * (1.f/DMODEL) - mu*mu + 1e-5f);
    const float4 gv = ((const float4*)g)[tid];
    const float4 bv = ((const float4*)b)[tid];
    float4 o4;
    o4.x = (v.x - mu)*inv*gv.x + bv.x;
    o4.y = (v.y - mu)*inv*gv.y + bv.y;
    o4.z = (v.z - mu)*inv*gv.z + bv.z;
    o4.w = (v.w - mu)*inv*gv.w + bv.w;
    ((float4*)(out + (size_t)row*DMODEL))[tid] = o4;
}

// ---------------- causal depthwise conv (DC=4) + bias + SiLU ----------------
__global__ void conv_silu_kernel(const float* __restrict__ xr,   // [MROWS, 2*DIN], xs part = cols [0,DIN)
                                 const float* __restrict__ cw,   // [DIN, DCONV]
                                 const float* __restrict__ cb,   // [DIN]
                                 float* __restrict__ xs)         // [MROWS, DIN]
{
    const int idx = blockIdx.x * blockDim.x + threadIdx.x;  // MROWS*DIN
    const int d   = idx & (DIN-1);
    const int row = idx >> 10;
    const int t   = row & (SEQ-1);
    float acc = cb[d];
    #pragma unroll
    for (int k = 0; k < DCONV; k++) {
        const int tt = t - (DCONV-1) + k;
        if (tt >= 0)
            acc = fmaf(cw[d*DCONV + k],
                       xr[((size_t)(row - (DCONV-1) + k))*(2*DIN) + d], acc);
    }
    xs[idx] = acc / (1.f + __expf(-acc));   // silu
}

// ---------------- selective scan: 1 warp per (b, di), 2 states per lane ----------------
#define SCHUNK 32
__global__ __launch_bounds__(256)
void scan_kernel(const float* __restrict__ xdbl,   // [MROWS,160]: dt|B|C
                 const float* __restrict__ dlt,    // [MROWS,DIN]
                 const float* __restrict__ xs,     // [MROWS,DIN]
                 const float* __restrict__ xr,     // [MROWS,2*DIN] (res2 = cols DIN..)
                 const float* __restrict__ A_log,  // [DIN,DSTATE]
                 const float* __restrict__ Dp,     // [DIN]
                 float* __restrict__ y)            // [MROWS,DIN]
{
    __shared__ float sBC[SCHUNK][2*DSTATE];   // B|C, 128 floats per step
    const int b    = blockIdx.y;
    const int warp = threadIdx.x >> 5;
    const int lane = threadIdx.x & 31;
    const int di   = blockIdx.x * 8 + warp;
    const float a0 = -__expf(A_log[di*DSTATE + lane]);
    const float a1 = -__expf(A_log[di*DSTATE + lane + 32]);
    const float dp = Dp[di];
    float h0 = 0.f, h1 = 0.f;
    const size_t base = (size_t)b * SEQ;

    for (int t0 = 0; t0 < SEQ; t0 += SCHUNK) {
        __syncthreads();
        for (int i = threadIdx.x; i < SCHUNK*2*DSTATE; i += 256) {
            const int r = i >> 7, c = i & 127;
            sBC[r][c] = xdbl[(base + t0 + r)*XPN + DRANK + c];
        }
        __syncthreads();
        for (int r = 0; r < SCHUNK; r++) {
            const size_t row = base + t0 + r;
            const float d_t = dlt[row*DIN + di];
            const float x_t = xs [row*DIN + di];
            const float bx  = d_t * x_t;
            h0 = fmaf(__expf(d_t * a0), h0, bx * sBC[r][lane]);
            h1 = fmaf(__expf(d_t * a1), h1, bx * sBC[r][lane + 32]);
            float yv = h0 * sBC[r][64 + lane] + h1 * sBC[r][96 + lane];
            #pragma unroll
            for (int o = 16; o; o >>= 1) yv += __shfl_xor_sync(0xffffffffu, yv, o);
            if (lane == 0) {
                const float r2 = xr[row*(2*DIN) + DIN + di];
                y[row*DIN + di] = (yv + x_t * dp) * (r2 / (1.f + __expf(-r2)));
            }
        }
    }
}

// ---------------- final tiny head: [4096,128] @ [5,128]^T + b ----------------
__global__ void head3_kernel(const float* __restrict__ hd2,
                             const float* __restrict__ w,
                             const float* __restrict__ b,
                             float* __restrict__ out)
{
    const int idx = blockIdx.x * blockDim.x + threadIdx.x;
    if (idx >= MROWS*NCLS) return;
    const int m = idx / NCLS, c = idx - m*NCLS;
    const float* hr = hd2 + (size_t)m*128;
    const float* wr = w + c*128;
    float acc = b[c];
    #pragma unroll 8
    for (int j = 0; j < 128; j++) acc = fmaf(hr[j], wr[j], acc);
    out[idx] = acc;
}

// ---------------- host orchestration ----------------
extern "C" void kernel_launch(void* const* d_in, const int* in_sizes, int n_in,
                              void* d_out, int out_size)
{
    (void)in_sizes; (void)n_in; (void)out_size;
    const int*   seq    = (const int*)  d_in[0];
    const float* be     = (const float*)d_in[1];
    const float* pe     = (const float*)d_in[2];
    const float* in_w   = (const float*)d_in[3];
    const float* in_b   = (const float*)d_in[4];
    const float* ln_g   = (const float*)d_in[5];
    const float* ln_b   = (const float*)d_in[6];
    const float* m_in_w = (const float*)d_in[7];
    const float* conv_w = (const float*)d_in[8];
    const float* conv_b = (const float*)d_in[9];
    const float* xp_w   = (const float*)d_in[10];
    const float* dt_w   = (const float*)d_in[11];
    const float* dt_b   = (const float*)d_in[12];
    const float* A_log  = (const float*)d_in[13];
    const float* Dp     = (const float*)d_in[14];
    const float* m_out_w= (const float*)d_in[15];
    const float* h1_w   = (const float*)d_in[16];
    const float* h1_b   = (const float*)d_in[17];
    const float* h2_w   = (const float*)d_in[18];
    const float* h2_b   = (const float*)d_in[19];
    const float* h3_w   = (const float*)d_in[20];
    const float* h3_b   = (const float*)d_in[21];
    float* out = (float*)d_out;

    float *xe,*x,*h,*xr,*xs,*xdbl,*dlt,*y,*hd1,*hd2;
    cudaGetSymbolAddress((void**)&xe,   g_xe);
    cudaGetSymbolAddress((void**)&x,    g_x);
    cudaGetSymbolAddress((void**)&h,    g_h);
    cudaGetSymbolAddress((void**)&xr,   g_xr);
    cudaGetSymbolAddress((void**)&xs,   g_xs);
    cudaGetSymbolAddress((void**)&xdbl, g_xdbl);
    cudaGetSymbolAddress((void**)&dlt,  g_dlt);
    cudaGetSymbolAddress((void**)&y,    g_y);
    cudaGetSymbolAddress((void**)&hd1,  g_hd1);
    cudaGetSymbolAddress((void**)&hd2,  g_hd2);

    // 1. embedding
    embed_kernel<<<MROWS*EMB/256, 256>>>(seq, be, pe, xe);

    // 2. input projection: x = xe @ in_w^T + in_b   [4096,512]
    sgemm_kernel<<<dim3(DMODEL/GBN, MROWS/GBM), 256>>>(
        xe, EMB, in_w, x, DMODEL, MROWS, DMODEL, EMB, in_b, nullptr, EPI_BIAS);

    for (int i = 0; i < NLAYER; i++) {
        // layernorm
        ln_kernel<<<MROWS, 128>>>(x, ln_g + (size_t)i*DMODEL, ln_b + (size_t)i*DMODEL, h);
        // xr = h @ m_in_w^T   [4096,2048]
        sgemm_kernel<<<dim3(2*DIN/GBN, MROWS/GBM), 256>>>(
            h, DMODEL, m_in_w + (size_t)i*2*DIN*DMODEL, xr, 2*DIN,
            MROWS, 2*DIN, DMODEL, nullptr, nullptr, EPI_NONE);
        // causal conv + silu -> xs
        conv_silu_kernel<<<MROWS*DIN/256, 256>>>(
            xr, conv_w + (size_t)i*DIN*DCONV, conv_b + (size_t)i*DIN, xs);
        // xdbl = xs @ xp_w^T   [4096,160]
        sgemm_kernel<<<dim3((XPN+GBN-1)/GBN, MROWS/GBM), 256>>>(
            xs, DIN, xp_w + (size_t)i*XPN*DIN, xdbl, XPN,
            MROWS, XPN, DIN, nullptr, nullptr, EPI_NONE);
        // delta = softplus(xdbl[:, :32] @ dt_w^T + dt_b)   [4096,1024]
        sgemm_kernel<<<dim3(DIN/GBN, MROWS/GBM), 256>>>(
            xdbl, XPN, dt_w + (size_t)i*DIN*DRANK, dlt, DIN,
            MROWS, DIN, DRANK, dt_b + (size_t)i*DIN, nullptr, EPI_BIAS_SOFTPLUS);
        // selective scan + Dp + gate -> y
        scan_kernel<<<dim3(DIN/8, BATCH), 256>>>(
            xdbl, dlt, xs, xr, A_log + (size_t)i*DIN*DSTATE, Dp + (size_t)i*DIN, y);
        // x = y @ m_out_w^T + x (residual)
        sgemm_kernel<<<dim3(DMODEL/GBN, MROWS/GBM), 256>>>(
            y, DIN, m_out_w + (size_t)i*DMODEL*DIN, x, DMODEL,
            MROWS, DMODEL, DIN, nullptr, x, EPI_RES);
    }

    // head
    sgemm_kernel<<<dim3(256/GBN, MROWS/GBM), 256>>>(
        x, DMODEL, h1_w, hd1, 256, MROWS, 256, DMODEL, h1_b, nullptr, EPI_BIAS_RELU);
    sgemm_kernel<<<dim3(1, MROWS/GBM), 256>>>(
        hd1, 256, h2_w, hd2, 128, MROWS, 128, 256, h2_b, nullptr, EPI_BIAS_RELU);
    head3_kernel<<<(MROWS*NCLS + 255)/256, 256>>>(hd2, h3_w, h3_b, out);
}

// round 2
// speedup vs baseline: 1.6839x; 1.6839x over previous
#include <cuda_runtime.h>
#include <math.h>

// ---------------- problem constants ----------------
#define BATCH  2
#define SEQ    2048
#define EMB    256
#define DMODEL 512
#define NLAYER 4
#define DIN    1024
#define DSTATE 64
#define DRANK  32
#define DCONV  4
#define NCLS   5
#define XPN    (DRANK + 2*DSTATE)   // 160
#define MROWS  (BATCH*SEQ)          // 4096
#define NCH    8                    // scan time-chunks
#define CLEN   (SEQ/NCH)            // 256

// ---------------- scratch (static device globals; no allocation) ----------------
__device__ float g_xe  [MROWS*EMB];
__device__ float g_x   [MROWS*DMODEL];
__device__ float g_h   [MROWS*DMODEL];
__device__ float g_xr  [MROWS*2*DIN];
__device__ float g_xs  [MROWS*DIN];
__device__ float g_xdbl[MROWS*XPN];
__device__ float g_dlt [MROWS*DIN];
__device__ float g_y   [MROWS*DIN];
__device__ float g_hd1 [MROWS*256];
__device__ float g_hd2 [MROWS*128];
__device__ float g_hchk  [BATCH*DIN*NCH*DSTATE];   // per-chunk local end state
__device__ float g_sumd  [BATCH*DIN*NCH];          // per-chunk sum of delta
__device__ float g_hstart[BATCH*DIN*NCH*DSTATE];   // corrected chunk start state

// ---------------- generic fp32 GEMM: C[M,N] = A[M,K] @ W[N,K]^T (+epilogue) ----------------
#define GBM 128
#define GBN 128
#define GBK 8
#define GTM 8
#define GTN 8

enum { EPI_NONE=0, EPI_BIAS=1, EPI_BIAS_RELU=2, EPI_BIAS_SOFTPLUS=3, EPI_RES=4 };

__global__ __launch_bounds__(256)
void sgemm_kernel(const float* __restrict__ A, int lda,
                  const float* __restrict__ Bw,           // [N,K], row-major
                  float* __restrict__ C, int ldc,
                  int M, int N, int K,
                  const float* __restrict__ bias,
                  const float* __restrict__ res,
                  int mode)
{
    __shared__ float As[GBK][GBM];
    __shared__ float Bs[GBK][GBN];
    const int tid  = threadIdx.x;
    const int bm   = blockIdx.y * GBM;
    const int bn   = blockIdx.x * GBN;
    const int tm   = (tid / 16) * GTM;
    const int tn   = (tid % 16) * GTN;
    const int lrow = tid >> 1;          // 0..127
    const int lk   = (tid & 1) * 4;     // 0 or 4

    float acc[GTM][GTN];
    #pragma unroll
    for (int i = 0; i < GTM; i++)
        #pragma unroll
        for (int j = 0; j < GTN; j++) acc[i][j] = 0.f;

    for (int k0 = 0; k0 < K; k0 += GBK) {
        float4 av = make_float4(0.f,0.f,0.f,0.f);
        float4 bv = make_float4(0.f,0.f,0.f,0.f);
        const int ar = bm + lrow;
        if (ar < M) av = *(const float4*)(A + (size_t)ar*lda + k0 + lk);
        const int br = bn + lrow;
        if (br < N) bv = *(const float4*)(Bw + (size_t)br*K + k0 + lk);
        As[lk+0][lrow]=av.x; As[lk+1][lrow]=av.y; As[lk+2][lrow]=av.z; As[lk+3][lrow]=av.w;
        Bs[lk+0][lrow]=bv.x; Bs[lk+1][lrow]=bv.y; Bs[lk+2][lrow]=bv.z; Bs[lk+3][lrow]=bv.w;
        __syncthreads();
        #pragma unroll
        for (int k = 0; k < GBK; k++) {
            float ra[GTM], rb[GTN];
            #pragma unroll
            for (int i = 0; i < GTM; i++) ra[i] = As[k][tm+i];
            #pragma unroll
            for (int j = 0; j < GTN; j++) rb[j] = Bs[k][tn+j];
            #pragma unroll
            for (int i = 0; i < GTM; i++)
                #pragma unroll
                for (int j = 0; j < GTN; j++)
                    acc[i][j] = fmaf(ra[i], rb[j], acc[i][j]);
        }
        __syncthreads();
    }

    #pragma unroll
    for (int i = 0; i < GTM; i++) {
        const int m = bm + tm + i;
        if (m >= M) continue;
        #pragma unroll
        for (int j = 0; j < GTN; j++) {
            const int n = bn + tn + j;
            if (n >= N) continue;
            float v = acc[i][j];
            if (mode == EPI_BIAS)            v += bias[n];
            else if (mode == EPI_BIAS_RELU)  { v += bias[n]; v = fmaxf(v, 0.f); }
            else if (mode == EPI_BIAS_SOFTPLUS) {
                v += bias[n];
                v = (v > 20.f) ? v : log1pf(expf(v));
            }
            else if (mode == EPI_RES)        v += res[(size_t)m*ldc + n];
            C[(size_t)m*ldc + n] = v;
        }
    }
}

// ---------------- embedding ----------------
__global__ void embed_kernel(const int* __restrict__ seq,
                             const float* __restrict__ be,
                             const float* __restrict__ pe,
                             float* __restrict__ xe)
{
    const int idx = blockIdx.x * blockDim.x + threadIdx.x;
    const int e   = idx & (EMB-1);
    const int row = idx >> 8;
    const int t   = row & (SEQ-1);
    const int by  = seq[row];
    xe[idx] = be[by*EMB + e] + pe[t*EMB + e];
}

// ---------------- layernorm over D=512 ----------------
__global__ void ln_kernel(const float* __restrict__ x,
                          const float* __restrict__ g,
                          const float* __restrict__ b,
                          float* __restrict__ out)
{
    const int row = blockIdx.x;
    const int tid = threadIdx.x;     // 128
    const float4 v = ((const float4*)(x + (size_t)row*DMODEL))[tid];
    float s  = v.x + v.y + v.z + v.w;
    float ss = v.x*v.x + v.y*v.y + v.z*v.z + v.w*v.w;
    #pragma unroll
    for (int o = 16; o; o >>= 1) {
        s  += __shfl_xor_sync(0xffffffffu, s,  o);
        ss += __shfl_xor_sync(0xffffffffu, ss, o);
    }
    __shared__ float sh_s[4], sh_ss[4];
    const int wid = tid >> 5, lane = tid & 31;
    if (lane == 0) { sh_s[wid] = s; sh_ss[wid] = ss; }
    __syncthreads();
    s  = sh_s[0] + sh_s[1] + sh_s[2] + sh_s[3];
    ss = sh_ss[0] + sh_ss[1] + sh_ss[2] + sh_ss[3];
    const float mu  = s * (1.f/DMODEL);
    const float inv = rsqrtf(ss * (1.f/DMODEL) - mu*mu + 1e-5f);
    const float4 gv = ((const float4*)g)[tid];
    const float4 bv = ((const float4*)b)[tid];
    float4 o4;
    o4.x = (v.x - mu)*inv*gv.x + bv.x;
    o4.y = (v.y - mu)*inv*gv.y + bv.y;
    o4.z = (v.z - mu)*inv*gv.z + bv.z;
    o4.w = (v.w - mu)*inv*gv.w + bv.w;
    ((float4*)(out + (size_t)row*DMODEL))[tid] = o4;
}

// ---------------- causal depthwise conv (DC=4) + bias + SiLU ----------------
__global__ void conv_silu_kernel(const float* __restrict__ xr,
                                 const float* __restrict__ cw,
                                 const float* __restrict__ cb,
                                 float* __restrict__ xs)
{
    const int idx = blockIdx.x * blockDim.x + threadIdx.x;
    const int d   = idx & (DIN-1);
    const int row = idx >> 10;
    const int t   = row & (SEQ-1);
    float acc = cb[d];
    #pragma unroll
    for (int k = 0; k < DCONV; k++) {
        const int tt = t - (DCONV-1) + k;
        if (tt >= 0)
            acc = fmaf(cw[d*DCONV + k],
                       xr[((size_t)(row - (DCONV-1) + k))*(2*DIN) + d], acc);
    }
    xs[idx] = acc / (1.f + __expf(-acc));
}

// =======================================================================
// Chunked parallel selective scan.
// Recurrence: h_t[s] = exp(d_t * a_s) * h_{t-1}[s] + (d_t*x_t) * B_t[s]
// Chunk transition: prod_t exp(d_t*a_s) = exp(a_s * sum_t d_t)  (exact)
// Pass1: per (b,di,chunk) compute local h (h0=0) + sum(d).
// Mid:   per (b,di) tiny 8-step scan over chunks -> hstart per chunk.
// Pass3: per (b,di,chunk) rerun with h=hstart, emit y (+Dp, gate).
// =======================================================================

__global__ __launch_bounds__(256)
void scan_pass1(const float* __restrict__ xdbl,
                const float* __restrict__ dlt,
                const float* __restrict__ xs,
                const float* __restrict__ A_log)
{
    __shared__ float sB[32][DSTATE];
    const int b    = blockIdx.z;
    const int ch   = blockIdx.y;
    const int warp = threadIdx.x >> 5;
    const int lane = threadIdx.x & 31;
    const int di   = blockIdx.x * 8 + warp;
    const float a0 = -__expf(A_log[di*DSTATE + lane]);
    const float a1 = -__expf(A_log[di*DSTATE + lane + 32]);
    float h0 = 0.f, h1 = 0.f, sd = 0.f;
    const size_t base = (size_t)b*SEQ + (size_t)ch*CLEN;

    for (int t0 = 0; t0 < CLEN; t0 += 32) {
        __syncthreads();
        for (int i = threadIdx.x; i < 32*DSTATE; i += 256) {
            const int r = i >> 6, c = i & 63;
            sB[r][c] = xdbl[(base + t0 + r)*XPN + DRANK + c];
        }
        __syncthreads();
        #pragma unroll 4
        for (int r = 0; r < 32; r++) {
            const size_t row = base + t0 + r;
            const float d_t = dlt[row*DIN + di];
            const float x_t = xs [row*DIN + di];
            const float bx  = d_t * x_t;
            sd += d_t;
            h0 = fmaf(__expf(d_t * a0), h0, bx * sB[r][lane]);
            h1 = fmaf(__expf(d_t * a1), h1, bx * sB[r][lane + 32]);
        }
    }
    const size_t o = (((size_t)b*DIN + di)*NCH + ch)*DSTATE;
    g_hchk[o + lane]      = h0;
    g_hchk[o + lane + 32] = h1;
    if (lane == 0) g_sumd[((size_t)b*DIN + di)*NCH + ch] = sd;
}

__global__ __launch_bounds__(256)
void scan_mid(const float* __restrict__ A_log)
{
    const int b    = blockIdx.z;
    const int warp = threadIdx.x >> 5;
    const int lane = threadIdx.x & 31;
    const int di   = blockIdx.x * 8 + warp;
    const float a0 = -__expf(A_log[di*DSTATE + lane]);
    const float a1 = -__expf(A_log[di*DSTATE + lane + 32]);
    float H0 = 0.f, H1 = 0.f;
    const size_t bd = (size_t)b*DIN + di;
    #pragma unroll
    for (int c = 0; c < NCH; c++) {
        const size_t o = (bd*NCH + c)*DSTATE;
        g_hstart[o + lane]      = H0;
        g_hstart[o + lane + 32] = H1;
        const float sd = g_sumd[bd*NCH + c];
        H0 = fmaf(__expf(sd * a0), H0, g_hchk[o + lane]);
        H1 = fmaf(__expf(sd * a1), H1, g_hchk[o + lane + 32]);
    }
}

__global__ __launch_bounds__(256)
void scan_pass3(const float* __restrict__ xdbl,
                const float* __restrict__ dlt,
                const float* __restrict__ xs,
                const float* __restrict__ xr,
                const float* __restrict__ A_log,
                const float* __restrict__ Dp,
                float* __restrict__ y)
{
    __shared__ float sBC[32][2*DSTATE];
    const int b    = blockIdx.z;
    const int ch   = blockIdx.y;
    const int warp = threadIdx.x >> 5;
    const int lane = threadIdx.x & 31;
    const int di   = blockIdx.x * 8 + warp;
    const float a0 = -__expf(A_log[di*DSTATE + lane]);
    const float a1 = -__expf(A_log[di*DSTATE + lane + 32]);
    const float dp = Dp[di];
    const size_t o = (((size_t)b*DIN + di)*NCH + ch)*DSTATE;
    float h0 = g_hstart[o + lane];
    float h1 = g_hstart[o + lane + 32];
    const size_t base = (size_t)b*SEQ + (size_t)ch*CLEN;

    for (int t0 = 0; t0 < CLEN; t0 += 32) {
        __syncthreads();
        for (int i = threadIdx.x; i < 32*2*DSTATE; i += 256) {
            const int r = i >> 7, c = i & 127;
            sBC[r][c] = xdbl[(base + t0 + r)*XPN + DRANK + c];
        }
        __syncthreads();
        for (int r = 0; r < 32; r++) {
            const size_t row = base + t0 + r;
            const float d_t = dlt[row*DIN + di];
            const float x_t = xs [row*DIN + di];
            const float bx  = d_t * x_t;
            h0 = fmaf(__expf(d_t * a0), h0, bx * sBC[r][lane]);
            h1 = fmaf(__expf(d_t * a1), h1, bx * sBC[r][lane + 32]);
            float yv = h0 * sBC[r][64 + lane] + h1 * sBC[r][96 + lane];
            #pragma unroll
            for (int off = 16; off; off >>= 1)
                yv += __shfl_xor_sync(0xffffffffu, yv, off);
            if (lane == 0) {
                const float r2 = xr[row*(2*DIN) + DIN + di];
                y[row*DIN + di] = (yv + x_t * dp) * (r2 / (1.f + __expf(-r2)));
            }
        }
    }
}

// ---------------- final tiny head: [4096,128] @ [5,128]^T + b ----------------
#define H3R 64
__global__ __launch_bounds__(320)
void head3_kernel(const float* __restrict__ hd2,
                  const float* __restrict__ w,
                  const float* __restrict__ b,
                  float* __restrict__ out)
{
    __shared__ float sh[H3R*132];        // padded rows (conflict-free)
    __shared__ float sw[NCLS*130];
    const int tid  = threadIdx.x;
    const int base = blockIdx.x * H3R;
    for (int i = tid; i < H3R*128; i += 320) {
        const int m = i >> 7, j = i & 127;
        sh[m*132 + j] = hd2[(size_t)(base + m)*128 + j];
    }
    for (int i = tid; i < NCLS*128; i += 320) {
        const int c = i >> 7, j = i & 127;
        sw[c*130 + j] = w[c*128 + j];
    }
    __syncthreads();
    const int m = tid / NCLS;
    const int c = tid - m*NCLS;
    float acc = b[c];
    #pragma unroll 8
    for (int j = 0; j < 128; j++)
        acc = fmaf(sh[m*132 + j], sw[c*130 + j], acc);
    out[(size_t)(base + m)*NCLS + c] = acc;
}

// ---------------- host orchestration ----------------
extern "C" void kernel_launch(void* const* d_in, const int* in_sizes, int n_in,
                              void* d_out, int out_size)
{
    (void)in_sizes; (void)n_in; (void)out_size;
    const int*   seq    = (const int*)  d_in[0];
    const float* be     = (const float*)d_in[1];
    const float* pe     = (const float*)d_in[2];
    const float* in_w   = (const float*)d_in[3];
    const float* in_b   = (const float*)d_in[4];
    const float* ln_g   = (const float*)d_in[5];
    const float* ln_b   = (const float*)d_in[6];
    const float* m_in_w = (const float*)d_in[7];
    const float* conv_w = (const float*)d_in[8];
    const float* conv_b = (const float*)d_in[9];
    const float* xp_w   = (const float*)d_in[10];
    const float* dt_w   = (const float*)d_in[11];
    const float* dt_b   = (const float*)d_in[12];
    const float* A_log  = (const float*)d_in[13];
    const float* Dp     = (const float*)d_in[14];
    const float* m_out_w= (const float*)d_in[15];
    const float* h1_w   = (const float*)d_in[16];
    const float* h1_b   = (const float*)d_in[17];
    const float* h2_w   = (const float*)d_in[18];
    const float* h2_b   = (const float*)d_in[19];
    const float* h3_w   = (const float*)d_in[20];
    const float* h3_b   = (const float*)d_in[21];
    float* out = (float*)d_out;

    float *xe,*x,*h,*xr,*xs,*xdbl,*dlt,*y,*hd1,*hd2;
    cudaGetSymbolAddress((void**)&xe,   g_xe);
    cudaGetSymbolAddress((void**)&x,    g_x);
    cudaGetSymbolAddress((void**)&h,    g_h);
    cudaGetSymbolAddress((void**)&xr,   g_xr);
    cudaGetSymbolAddress((void**)&xs,   g_xs);
    cudaGetSymbolAddress((void**)&xdbl, g_xdbl);
    cudaGetSymbolAddress((void**)&dlt,  g_dlt);
    cudaGetSymbolAddress((void**)&y,    g_y);
    cudaGetSymbolAddress((void**)&hd1,  g_hd1);
    cudaGetSymbolAddress((void**)&hd2,  g_hd2);

    embed_kernel<<<MROWS*EMB/256, 256>>>(seq, be, pe, xe);
    sgemm_kernel<<<dim3(DMODEL/GBN, MROWS/GBM), 256>>>(
        xe, EMB, in_w, x, DMODEL, MROWS, DMODEL, EMB, in_b, nullptr, EPI_BIAS);

    for (int i = 0; i < NLAYER; i++) {
        ln_kernel<<<MROWS, 128>>>(x, ln_g + (size_t)i*DMODEL, ln_b + (size_t)i*DMODEL, h);
        sgemm_kernel<<<dim3(2*DIN/GBN, MROWS/GBM), 256>>>(
            h, DMODEL, m_in_w + (size_t)i*2*DIN*DMODEL, xr, 2*DIN,
            MROWS, 2*DIN, DMODEL, nullptr, nullptr, EPI_NONE);
        conv_silu_kernel<<<MROWS*DIN/256, 256>>>(
            xr, conv_w + (size_t)i*DIN*DCONV, conv_b + (size_t)i*DIN, xs);
        sgemm_kernel<<<dim3((XPN+GBN-1)/GBN, MROWS/GBM), 256>>>(
            xs, DIN, xp_w + (size_t)i*XPN*DIN, xdbl, XPN,
            MROWS, XPN, DIN, nullptr, nullptr, EPI_NONE);
        sgemm_kernel<<<dim3(DIN/GBN, MROWS/GBM), 256>>>(
            xdbl, XPN, dt_w + (size_t)i*DIN*DRANK, dlt, DIN,
            MROWS, DIN, DRANK, dt_b + (size_t)i*DIN, nullptr, EPI_BIAS_SOFTPLUS);
        // chunked parallel scan
        scan_pass1<<<dim3(DIN/8, NCH, BATCH), 256>>>(
            xdbl, dlt, xs, A_log + (size_t)i*DIN*DSTATE);
        scan_mid<<<dim3(DIN/8, 1, BATCH), 256>>>(A_log + (size_t)i*DIN*DSTATE);
        scan_pass3<<<dim3(DIN/8, NCH, BATCH), 256>>>(
            xdbl, dlt, xs, xr, A_log + (size_t)i*DIN*DSTATE, Dp + (size_t)i*DIN, y);
        sgemm_kernel<<<dim3(DMODEL/GBN, MROWS/GBM), 256>>>(
            y, DIN, m_out_w + (size_t)i*DMODEL*DIN, x, DMODEL,
            MROWS, DMODEL, DIN, nullptr, x, EPI_RES);
    }

    sgemm_kernel<<<dim3(256/GBN, MROWS/GBM), 256>>>(
        x, DMODEL, h1_w, hd1, 256, MROWS, 256, DMODEL, h1_b, nullptr, EPI_BIAS_RELU);
    sgemm_kernel<<<dim3(1, MROWS/GBM), 256>>>(
        hd1, 256, h2_w, hd2, 128, MROWS, 128, 256, h2_b, nullptr, EPI_BIAS_RELU);
    head3_kernel<<<MROWS/H3R, 320>>>(hd2, h3_w, h3_b, out);
}

// round 3
// speedup vs baseline: 2.0780x; 1.2341x over previous
#include <cuda_runtime.h>
#include <math.h>
#include <stdint.h>

// ---------------- problem constants ----------------
#define BATCH  2
#define SEQ    2048
#define EMB    256
#define DMODEL 512
#define NLAYER 4
#define DIN    1024
#define DSTATE 64
#define DRANK  32
#define DCONV  4
#define NCLS   5
#define XPN    (DRANK + 2*DSTATE)   // 160
#define MROWS  (BATCH*SEQ)          // 4096
#define NCH    8                    // scan time-chunks
#define CLEN   (SEQ/NCH)            // 256

// ---------------- scratch ----------------
__device__ float g_xe  [MROWS*EMB];
__device__ float g_x   [MROWS*DMODEL];
__device__ float g_h   [MROWS*DMODEL];
__device__ float g_xr  [MROWS*2*DIN];
__device__ float g_xs  [MROWS*DIN];
__device__ float g_xdbl[MROWS*XPN];
__device__ float g_dlt [MROWS*DIN];
__device__ float g_y   [MROWS*DIN];
__device__ float g_hd1 [MROWS*256];
__device__ float g_hd2 [MROWS*128];
__device__ float g_hchk  [BATCH*DIN*NCH*DSTATE];
__device__ float g_sumd  [BATCH*DIN*NCH];
__device__ float g_hstart[BATCH*DIN*NCH*DSTATE];

enum { EPI_NONE=0, EPI_BIAS=1, EPI_BIAS_RELU=2, EPI_BIAS_SOFTPLUS=3, EPI_RES=4 };

// ===================== tf32x3 tensor-core GEMM =====================
// C[M,N] = A[M,K] @ W[N,K]^T, fp32 in/out, tf32 split (hi+lo) for fp32-level
// accuracy. Tiles: 128x128x16, 8 warps (2x4), warp tile 64x32, mma m16n8k8.
#define TBM 128
#define TBN 128
#define TBK 16
#define APITCH 28   // row pitch (floats): conflict-free frag LDS, aligned STS.128

__device__ __forceinline__ uint32_t f2tf(float x) {
    uint32_t r; asm("cvt.rna.tf32.f32 %0, %1;" : "=r"(r) : "f"(x)); return r;
}
__device__ __forceinline__ void split_tf(float x, uint32_t& hi, uint32_t& lo) {
    hi = f2tf(x);
    lo = f2tf(x - __uint_as_float(hi));
}
__device__ __forceinline__ void mma_tf32(float* c, const uint32_t* a, const uint32_t* b) {
    asm volatile(
        "mma.sync.aligned.m16n8k8.row.col.f32.tf32.tf32.f32 "
        "{%0,%1,%2,%3}, {%4,%5,%6,%7}, {%8,%9}, {%0,%1,%2,%3};"
        : "+f"(c[0]), "+f"(c[1]), "+f"(c[2]), "+f"(c[3])
        : "r"(a[0]), "r"(a[1]), "r"(a[2]), "r"(a[3]), "r"(b[0]), "r"(b[1]));
}

__global__ __launch_bounds__(256)
void gemm_tc(const float* __restrict__ A, int lda,
             const float* __restrict__ W,            // [N,K] row-major
             float* __restrict__ C, int ldc,
             int M, int N, int K,
             const float* __restrict__ bias,
             const float* __restrict__ res,
             int mode)
{
    __shared__ float As[TBM*APITCH];
    __shared__ float Bs[TBN*APITCH];
    const int tid   = threadIdx.x;
    const int lane  = tid & 31;
    const int wid   = tid >> 5;
    const int warp_m = wid >> 2;       // 0..1  (64 rows)
    const int warp_n = wid & 3;        // 0..3  (32 cols)
    const int quad  = lane >> 2;       // 0..7
    const int ql    = lane & 3;        // 0..3
    const int bm    = blockIdx.y * TBM;
    const int bn    = blockIdx.x * TBN;

    float acc[4][4][4];
    #pragma unroll
    for (int i = 0; i < 4; i++)
        #pragma unroll
        for (int j = 0; j < 4; j++)
            #pragma unroll
            for (int k = 0; k < 4; k++) acc[i][j][k] = 0.f;

    for (int k0 = 0; k0 < K; k0 += TBK) {
        // stage A tile [128 rows][16 k] and B tile, non-transposed, pitch 28
        #pragma unroll
        for (int i = 0; i < 2; i++) {
            const int idx = tid + i*256;         // 0..511
            const int r   = idx >> 2;            // 0..127
            const int kq  = (idx & 3) * 4;       // 0,4,8,12
            const float4 av = *(const float4*)(A + (size_t)(bm + r)*lda + k0 + kq);
            *(float4*)(&As[r*APITCH + kq]) = av;
            float4 bv = make_float4(0.f,0.f,0.f,0.f);
            if (bn + r < N) bv = *(const float4*)(W + (size_t)(bn + r)*K + k0 + kq);
            *(float4*)(&Bs[r*APITCH + kq]) = bv;
        }
        __syncthreads();

        #pragma unroll
        for (int ks = 0; ks < 2; ks++) {
            const int kb = ks*8 + ql;
            uint32_t ahi[4][4], alo[4][4], bhi[4][2], blo[4][2];
            #pragma unroll
            for (int mt = 0; mt < 4; mt++) {
                const int r0 = warp_m*64 + mt*16 + quad;
                split_tf(As[ r0     *APITCH + kb    ], ahi[mt][0], alo[mt][0]);
                split_tf(As[(r0 + 8)*APITCH + kb    ], ahi[mt][1], alo[mt][1]);
                split_tf(As[ r0     *APITCH + kb + 4], ahi[mt][2], alo[mt][2]);
                split_tf(As[(r0 + 8)*APITCH + kb + 4], ahi[mt][3], alo[mt][3]);
            }
            #pragma unroll
            for (int nt = 0; nt < 4; nt++) {
                const int c0 = warp_n*32 + nt*8 + quad;
                split_tf(Bs[c0*APITCH + kb    ], bhi[nt][0], blo[nt][0]);
                split_tf(Bs[c0*APITCH + kb + 4], bhi[nt][1], blo[nt][1]);
            }
            #pragma unroll
            for (int mt = 0; mt < 4; mt++)
                #pragma unroll
                for (int nt = 0; nt < 4; nt++) {
                    mma_tf32(acc[mt][nt], ahi[mt], blo[nt]);
                    mma_tf32(acc[mt][nt], alo[mt], bhi[nt]);
                    mma_tf32(acc[mt][nt], ahi[mt], bhi[nt]);
                }
        }
        __syncthreads();
    }

    // epilogue (M is always a multiple of 128 here; guard N only)
    #pragma unroll
    for (int mt = 0; mt < 4; mt++) {
        const int r0 = bm + warp_m*64 + mt*16 + quad;
        #pragma unroll
        for (int nt = 0; nt < 4; nt++) {
            const int cb = bn + warp_n*32 + nt*8 + 2*ql;
            if (cb >= N) continue;
            float v[4] = {acc[mt][nt][0], acc[mt][nt][1], acc[mt][nt][2], acc[mt][nt][3]};
            if (mode == EPI_BIAS || mode == EPI_BIAS_RELU || mode == EPI_BIAS_SOFTPLUS) {
                const float b0 = bias[cb], b1 = bias[cb+1];
                v[0] += b0; v[1] += b1; v[2] += b0; v[3] += b1;
                if (mode == EPI_BIAS_RELU) {
                    #pragma unroll
                    for (int q = 0; q < 4; q++) v[q] = fmaxf(v[q], 0.f);
                } else if (mode == EPI_BIAS_SOFTPLUS) {
                    #pragma unroll
                    for (int q = 0; q < 4; q++)
                        v[q] = (v[q] > 20.f) ? v[q] : log1pf(expf(v[q]));
                }
            } else if (mode == EPI_RES) {
                const float2 r0v = *(const float2*)(res + (size_t)r0*ldc + cb);
                const float2 r1v = *(const float2*)(res + (size_t)(r0+8)*ldc + cb);
                v[0] += r0v.x; v[1] += r0v.y; v[2] += r1v.x; v[3] += r1v.y;
            }
            *(float2*)(C + (size_t)r0*ldc + cb)     = make_float2(v[0], v[1]);
            *(float2*)(C + (size_t)(r0+8)*ldc + cb) = make_float2(v[2], v[3]);
        }
    }
}

// ---------------- embedding ----------------
__global__ void embed_kernel(const int* __restrict__ seq,
                             const float* __restrict__ be,
                             const float* __restrict__ pe,
                             float* __restrict__ xe)
{
    const int idx = blockIdx.x * blockDim.x + threadIdx.x;
    const int e   = idx & (EMB-1);
    const int row = idx >> 8;
    const int t   = row & (SEQ-1);
    const int by  = seq[row];
    xe[idx] = be[by*EMB + e] + pe[t*EMB + e];
}

// ---------------- layernorm over D=512 ----------------
__global__ void ln_kernel(const float* __restrict__ x,
                          const float* __restrict__ g,
                          const float* __restrict__ b,
                          float* __restrict__ out)
{
    const int row = blockIdx.x;
    const int tid = threadIdx.x;     // 128
    const float4 v = ((const float4*)(x + (size_t)row*DMODEL))[tid];
    float s  = v.x + v.y + v.z + v.w;
    float ss = v.x*v.x + v.y*v.y + v.z*v.z + v.w*v.w;
    #pragma unroll
    for (int o = 16; o; o >>= 1) {
        s  += __shfl_xor_sync(0xffffffffu, s,  o);
        ss += __shfl_xor_sync(0xffffffffu, ss, o);
    }
    __shared__ float sh_s[4], sh_ss[4];
    const int wid = tid >> 5, lane = tid & 31;
    if (lane == 0) { sh_s[wid] = s; sh_ss[wid] = ss; }
    __syncthreads();
    s  = sh_s[0] + sh_s[1] + sh_s[2] + sh_s[3];
    ss = sh_ss[0] + sh_ss[1] + sh_ss[2] + sh_ss[3];
    const float mu  = s * (1.f/DMODEL);
    const float inv = rsqrtf(ss * (1.f/DMODEL) - mu*mu + 1e-5f);
    const float4 gv = ((const float4*)g)[tid];
    const float4 bv = ((const float4*)b)[tid];
    float4 o4;
    o4.x = (v.x - mu)*inv*gv.x + bv.x;
    o4.y = (v.y - mu)*inv*gv.y + bv.y;
    o4.z = (v.z - mu)*inv*gv.z + bv.z;
    o4.w = (v.w - mu)*inv*gv.w + bv.w;
    ((float4*)(out + (size_t)row*DMODEL))[tid] = o4;
}

// ---------------- causal depthwise conv (DC=4) + bias + SiLU ----------------
__global__ void conv_silu_kernel(const float* __restrict__ xr,
                                 const float* __restrict__ cw,
                                 const float* __restrict__ cb,
                                 float* __restrict__ xs)
{
    const int idx = blockIdx.x * blockDim.x + threadIdx.x;
    const int d   = idx & (DIN-1);
    const int row = idx >> 10;
    const int t   = row & (SEQ-1);
    float acc = cb[d];
    #pragma unroll
    for (int k = 0; k < DCONV; k++) {
        const int tt = t - (DCONV-1) + k;
        if (tt >= 0)
            acc = fmaf(cw[d*DCONV + k],
                       xr[((size_t)(row - (DCONV-1) + k))*(2*DIN) + d], acc);
    }
    xs[idx] = acc / (1.f + __expf(-acc));
}

// ===================== chunked parallel selective scan =====================
__global__ __launch_bounds__(256)
void scan_pass1(const float* __restrict__ xdbl,
                const float* __restrict__ dlt,
                const float* __restrict__ xs,
                const float* __restrict__ A_log)
{
    __shared__ float sB[32][DSTATE];
    const int b    = blockIdx.z;
    const int ch   = blockIdx.y;
    const int warp = threadIdx.x >> 5;
    const int lane = threadIdx.x & 31;
    const int di   = blockIdx.x * 8 + warp;
    const float a0 = -__expf(A_log[di*DSTATE + lane]);
    const float a1 = -__expf(A_log[di*DSTATE + lane + 32]);
    float h0 = 0.f, h1 = 0.f, sd = 0.f;
    const size_t base = (size_t)b*SEQ + (size_t)ch*CLEN;

    for (int t0 = 0; t0 < CLEN; t0 += 32) {
        __syncthreads();
        for (int i = threadIdx.x; i < 32*DSTATE; i += 256) {
            const int r = i >> 6, c = i & 63;
            sB[r][c] = xdbl[(base + t0 + r)*XPN + DRANK + c];
        }
        __syncthreads();
        #pragma unroll 4
        for (int r = 0; r < 32; r++) {
            const size_t row = base + t0 + r;
            const float d_t = dlt[row*DIN + di];
            const float x_t = xs [row*DIN + di];
            const float bx  = d_t * x_t;
            sd += d_t;
            h0 = fmaf(__expf(d_t * a0), h0, bx * sB[r][lane]);
            h1 = fmaf(__expf(d_t * a1), h1, bx * sB[r][lane + 32]);
        }
    }
    const size_t o = (((size_t)b*DIN + di)*NCH + ch)*DSTATE;
    g_hchk[o + lane]      = h0;
    g_hchk[o + lane + 32] = h1;
    if (lane == 0) g_sumd[((size_t)b*DIN + di)*NCH + ch] = sd;
}

__global__ __launch_bounds__(256)
void scan_mid(const float* __restrict__ A_log)
{
    const int b    = blockIdx.z;
    const int warp = threadIdx.x >> 5;
    const int lane = threadIdx.x & 31;
    const int di   = blockIdx.x * 8 + warp;
    const float a0 = -__expf(A_log[di*DSTATE + lane]);
    const float a1 = -__expf(A_log[di*DSTATE + lane + 32]);
    float H0 = 0.f, H1 = 0.f;
    const size_t bd = (size_t)b*DIN + di;
    #pragma unroll
    for (int c = 0; c < NCH; c++) {
        const size_t o = (bd*NCH + c)*DSTATE;
        g_hstart[o + lane]      = H0;
        g_hstart[o + lane + 32] = H1;
        const float sd = g_sumd[bd*NCH + c];
        H0 = fmaf(__expf(sd * a0), H0, g_hchk[o + lane]);
        H1 = fmaf(__expf(sd * a1), H1, g_hchk[o + lane + 32]);
    }
}

__global__ __launch_bounds__(256)
void scan_pass3(const float* __restrict__ xdbl,
                const float* __restrict__ dlt,
                const float* __restrict__ xs,
                const float* __restrict__ xr,
                const float* __restrict__ A_log,
                const float* __restrict__ Dp,
                float* __restrict__ y)
{
    __shared__ float sBC[32][2*DSTATE];
    const int b    = blockIdx.z;
    const int ch   = blockIdx.y;
    const int warp = threadIdx.x >> 5;
    const int lane = threadIdx.x & 31;
    const int di   = blockIdx.x * 8 + warp;
    const float a0 = -__expf(A_log[di*DSTATE + lane]);
    const float a1 = -__expf(A_log[di*DSTATE + lane + 32]);
    const float dp = Dp[di];
    const size_t o = (((size_t)b*DIN + di)*NCH + ch)*DSTATE;
    float h0 = g_hstart[o + lane];
    float h1 = g_hstart[o + lane + 32];
    const size_t base = (size_t)b*SEQ + (size_t)ch*CLEN;

    for (int t0 = 0; t0 < CLEN; t0 += 32) {
        __syncthreads();
        for (int i = threadIdx.x; i < 32*2*DSTATE; i += 256) {
            const int r = i >> 7, c = i & 127;
            sBC[r][c] = xdbl[(base + t0 + r)*XPN + DRANK + c];
        }
        __syncthreads();
        for (int r = 0; r < 32; r++) {
            const size_t row = base + t0 + r;
            const float d_t = dlt[row*DIN + di];
            const float x_t = xs [row*DIN + di];
            const float bx  = d_t * x_t;
            h0 = fmaf(__expf(d_t * a0), h0, bx * sBC[r][lane]);
            h1 = fmaf(__expf(d_t * a1), h1, bx * sBC[r][lane + 32]);
            float yv = h0 * sBC[r][64 + lane] + h1 * sBC[r][96 + lane];
            #pragma unroll
            for (int off = 16; off; off >>= 1)
                yv += __shfl_xor_sync(0xffffffffu, yv, off);
            if (lane == 0) {
                const float r2 = xr[row*(2*DIN) + DIN + di];
                y[row*DIN + di] = (yv + x_t * dp) * (r2 / (1.f + __expf(-r2)));
            }
        }
    }
}

// ---------------- final tiny head ----------------
#define H3R 64
__global__ __launch_bounds__(320)
void head3_kernel(const float* __restrict__ hd2,
                  const float* __restrict__ w,
                  const float* __restrict__ b,
                  float* __restrict__ out)
{
    __shared__ float sh[H3R*132];
    __shared__ float sw[NCLS*130];
    const int tid  = threadIdx.x;
    const int base = blockIdx.x * H3R;
    for (int i = tid; i < H3R*128; i += 320) {
        const int m = i >> 7, j = i & 127;
        sh[m*132 + j] = hd2[(size_t)(base + m)*128 + j];
    }
    for (int i = tid; i < NCLS*128; i += 320) {
        const int c = i >> 7, j = i & 127;
        sw[c*130 + j] = w[c*128 + j];
    }
    __syncthreads();
    const int m = tid / NCLS;
    const int c = tid - m*NCLS;
    float acc = b[c];
    #pragma unroll 8
    for (int j = 0; j < 128; j++)
        acc = fmaf(sh[m*132 + j], sw[c*130 + j], acc);
    out[(size_t)(base + m)*NCLS + c] = acc;
}

// ---------------- host orchestration ----------------
extern "C" void kernel_launch(void* const* d_in, const int* in_sizes, int n_in,
                              void* d_out, int out_size)
{
    (void)in_sizes; (void)n_in; (void)out_size;
    const int*   seq    = (const int*)  d_in[0];
    const float* be     = (const float*)d_in[1];
    const float* pe     = (const float*)d_in[2];
    const float* in_w   = (const float*)d_in[3];
    const float* in_b   = (const float*)d_in[4];
    const float* ln_g   = (const float*)d_in[5];
    const float* ln_b   = (const float*)d_in[6];
    const float* m_in_w = (const float*)d_in[7];
    const float* conv_w = (const float*)d_in[8];
    const float* conv_b = (const float*)d_in[9];
    const float* xp_w   = (const float*)d_in[10];
    const float* dt_w   = (const float*)d_in[11];
    const float* dt_b   = (const float*)d_in[12];
    const float* A_log  = (const float*)d_in[13];
    const float* Dp     = (const float*)d_in[14];
    const float* m_out_w= (const float*)d_in[15];
    const float* h1_w   = (const float*)d_in[16];
    const float* h1_b   = (const float*)d_in[17];
    const float* h2_w   = (const float*)d_in[18];
    const float* h2_b   = (const float*)d_in[19];
    const float* h3_w   = (const float*)d_in[20];
    const float* h3_b   = (const float*)d_in[21];
    float* out = (float*)d_out;

    float *xe,*x,*h,*xr,*xs,*xdbl,*dlt,*y,*hd1,*hd2;
    cudaGetSymbolAddress((void**)&xe,   g_xe);
    cudaGetSymbolAddress((void**)&x,    g_x);
    cudaGetSymbolAddress((void**)&h,    g_h);
    cudaGetSymbolAddress((void**)&xr,   g_xr);
    cudaGetSymbolAddress((void**)&xs,   g_xs);
    cudaGetSymbolAddress((void**)&xdbl, g_xdbl);
    cudaGetSymbolAddress((void**)&dlt,  g_dlt);
    cudaGetSymbolAddress((void**)&y,    g_y);
    cudaGetSymbolAddress((void**)&hd1,  g_hd1);
    cudaGetSymbolAddress((void**)&hd2,  g_hd2);

    embed_kernel<<<MROWS*EMB/256, 256>>>(seq, be, pe, xe);
    gemm_tc<<<dim3(DMODEL/TBN, MROWS/TBM), 256>>>(
        xe, EMB, in_w, x, DMODEL, MROWS, DMODEL, EMB, in_b, nullptr, EPI_BIAS);

    for (int i = 0; i < NLAYER; i++) {
        ln_kernel<<<MROWS, 128>>>(x, ln_g + (size_t)i*DMODEL, ln_b + (size_t)i*DMODEL, h);
        gemm_tc<<<dim3(2*DIN/TBN, MROWS/TBM), 256>>>(
            h, DMODEL, m_in_w + (size_t)i*2*DIN*DMODEL, xr, 2*DIN,
            MROWS, 2*DIN, DMODEL, nullptr, nullptr, EPI_NONE);
        conv_silu_kernel<<<MROWS*DIN/256, 256>>>(
            xr, conv_w + (size_t)i*DIN*DCONV, conv_b + (size_t)i*DIN, xs);
        gemm_tc<<<dim3((XPN+TBN-1)/TBN, MROWS/TBM), 256>>>(
            xs, DIN, xp_w + (size_t)i*XPN*DIN, xdbl, XPN,
            MROWS, XPN, DIN, nullptr, nullptr, EPI_NONE);
        gemm_tc<<<dim3(DIN/TBN, MROWS/TBM), 256>>>(
            xdbl, XPN, dt_w + (size_t)i*DIN*DRANK, dlt, DIN,
            MROWS, DIN, DRANK, dt_b + (size_t)i*DIN, nullptr, EPI_BIAS_SOFTPLUS);
        scan_pass1<<<dim3(DIN/8, NCH, BATCH), 256>>>(
            xdbl, dlt, xs, A_log + (size_t)i*DIN*DSTATE);
        scan_mid<<<dim3(DIN/8, 1, BATCH), 256>>>(A_log + (size_t)i*DIN*DSTATE);
        scan_pass3<<<dim3(DIN/8, NCH, BATCH), 256>>>(
            xdbl, dlt, xs, xr, A_log + (size_t)i*DIN*DSTATE, Dp + (size_t)i*DIN, y);
        gemm_tc<<<dim3(DMODEL/TBN, MROWS/TBM), 256>>>(
            y, DIN, m_out_w + (size_t)i*DMODEL*DIN, x, DMODEL,
            MROWS, DMODEL, DIN, nullptr, x, EPI_RES);
    }

    gemm_tc<<<dim3(256/TBN, MROWS/TBM), 256>>>(
        x, DMODEL, h1_w, hd1, 256, MROWS, 256, DMODEL, h1_b, nullptr, EPI_BIAS_RELU);
    gemm_tc<<<dim3(1, MROWS/TBM), 256>>>(
        hd1, 256, h2_w, hd2, 128, MROWS, 128, 256, h2_b, nullptr, EPI_BIAS_RELU);
    head3_kernel<<<MROWS/H3R, 320>>>(hd2, h3_w, h3_b, out);
}

// round 4
// speedup vs baseline: 2.2898x; 1.1019x over previous
#include <cuda_runtime.h>
#include <math.h>
#include <stdint.h>

// ---------------- problem constants ----------------
#define BATCH  2
#define SEQ    2048
#define EMB    256
#define DMODEL 512
#define NLAYER 4
#define DIN    1024
#define DSTATE 64
#define DRANK  32
#define DCONV  4
#define NCLS   5
#define XPN    (DRANK + 2*DSTATE)   // 160
#define MROWS  (BATCH*SEQ)          // 4096
#define NCH    8
#define CLEN   (SEQ/NCH)            // 256

// ---------------- scratch ----------------
__device__ float g_xe  [MROWS*EMB];
__device__ float g_x   [MROWS*DMODEL];
__device__ float g_h   [MROWS*DMODEL];
__device__ float g_xr  [MROWS*2*DIN];
__device__ float g_xs  [MROWS*DIN];
__device__ float g_xdbl[MROWS*XPN];
__device__ float g_dlt [MROWS*DIN];
__device__ float g_y   [MROWS*DIN];
__device__ float g_hd1 [MROWS*256];
__device__ float g_hd2 [MROWS*128];
__device__ float g_hchk  [BATCH*DIN*NCH*DSTATE];
__device__ float g_sumd  [BATCH*DIN*NCH];
__device__ float g_hstart[BATCH*DIN*NCH*DSTATE];

enum { EPI_NONE=0, EPI_BIAS=1, EPI_BIAS_RELU=2, EPI_BIAS_SOFTPLUS=3, EPI_RES=4 };

// ===================== tf32x3 tensor-core GEMM =====================
// C[M,N] = A[M,K] @ W[N,K]^T. tf32 split (hi+lo) staged into SMEM once per
// tile (conversion OFF the mainloop critical path). Mainloop = LDS + HMMA only.
// Template TM = block rows (128 or 64). 8 warps (2 x 4), warp tile (TM/2) x 32.
#define TBN 128
#define TBK 16
#define APITCH 28   // conflict-free pitch for fragment LDS; 16B-aligned STS.128

__device__ __forceinline__ uint32_t f2tf(float x) {
    uint32_t r; asm("cvt.rna.tf32.f32 %0, %1;" : "=r"(r) : "f"(x)); return r;
}
__device__ __forceinline__ void split4(float4 v, float4& hi, float4& lo) {
    uint32_t hx = f2tf(v.x), hy = f2tf(v.y), hz = f2tf(v.z), hw = f2tf(v.w);
    hi = make_float4(__uint_as_float(hx), __uint_as_float(hy),
                     __uint_as_float(hz), __uint_as_float(hw));
    lo = make_float4(__uint_as_float(f2tf(v.x - __uint_as_float(hx))),
                     __uint_as_float(f2tf(v.y - __uint_as_float(hy))),
                     __uint_as_float(f2tf(v.z - __uint_as_float(hz))),
                     __uint_as_float(f2tf(v.w - __uint_as_float(hw))));
}
__device__ __forceinline__ void mma_tf32(float* c, const uint32_t* a, const uint32_t* b) {
    asm volatile(
        "mma.sync.aligned.m16n8k8.row.col.f32.tf32.tf32.f32 "
        "{%0,%1,%2,%3}, {%4,%5,%6,%7}, {%8,%9}, {%0,%1,%2,%3};"
        : "+f"(c[0]), "+f"(c[1]), "+f"(c[2]), "+f"(c[3])
        : "r"(a[0]), "r"(a[1]), "r"(a[2]), "r"(a[3]), "r"(b[0]), "r"(b[1]));
}

template<int TM>
__global__ __launch_bounds__(256)
void gemm_tc(const float* __restrict__ A, int lda,
             const float* __restrict__ W,            // [N,K] row-major
             float* __restrict__ C, int ldc,
             int M, int N, int K,
             const float* __restrict__ bias,
             const float* __restrict__ res,
             int mode)
{
    constexpr int MT  = TM / 32;        // m16 tiles per warp (4 or 2)
    constexpr int AIT = (TM * 4) / 256; // float4 A loads per thread (2 or 1)

    extern __shared__ float smem[];
    float* AsH = smem;
    float* AsL = AsH + TM  * APITCH;
    float* BsH = AsL + TM  * APITCH;
    float* BsL = BsH + TBN * APITCH;

    const int tid    = threadIdx.x;
    const int lane   = tid & 31;
    const int wid    = tid >> 5;
    const int warp_m = wid >> 2;        // 0..1
    const int warp_n = wid & 3;         // 0..3
    const int quad   = lane >> 2;       // 0..7
    const int ql     = lane & 3;        // 0..3
    const int bm     = blockIdx.y * TM;
    const int bn     = blockIdx.x * TBN;

    float acc[MT][4][4];
    #pragma unroll
    for (int i = 0; i < MT; i++)
        #pragma unroll
        for (int j = 0; j < 4; j++)
            #pragma unroll
            for (int k = 0; k < 4; k++) acc[i][j][k] = 0.f;

    float4 pa[AIT], pb[2];

    // prefetch tile 0
    #pragma unroll
    for (int i = 0; i < AIT; i++) {
        const int idx = tid + i*256, r = idx >> 2, kq = (idx & 3)*4;
        pa[i] = *(const float4*)(A + (size_t)(bm + r)*lda + kq);
    }
    #pragma unroll
    for (int i = 0; i < 2; i++) {
        const int idx = tid + i*256, r = idx >> 2, kq = (idx & 3)*4;
        pb[i] = (bn + r < N) ? *(const float4*)(W + (size_t)(bn + r)*K + kq)
                             : make_float4(0.f,0.f,0.f,0.f);
    }

    for (int k0 = 0; k0 < K; k0 += TBK) {
        // stage with split (convert once per element)
        #pragma unroll
        for (int i = 0; i < AIT; i++) {
            const int idx = tid + i*256, r = idx >> 2, kq = (idx & 3)*4;
            float4 hi, lo; split4(pa[i], hi, lo);
            *(float4*)(&AsH[r*APITCH + kq]) = hi;
            *(float4*)(&AsL[r*APITCH + kq]) = lo;
        }
        #pragma unroll
        for (int i = 0; i < 2; i++) {
            const int idx = tid + i*256, r = idx >> 2, kq = (idx & 3)*4;
            float4 hi, lo; split4(pb[i], hi, lo);
            *(float4*)(&BsH[r*APITCH + kq]) = hi;
            *(float4*)(&BsL[r*APITCH + kq]) = lo;
        }
        __syncthreads();

        // prefetch next tile into registers (overlaps with MMA below)
        if (k0 + TBK < K) {
            #pragma unroll
            for (int i = 0; i < AIT; i++) {
                const int idx = tid + i*256, r = idx >> 2, kq = (idx & 3)*4;
                pa[i] = *(const float4*)(A + (size_t)(bm + r)*lda + k0 + TBK + kq);
            }
            #pragma unroll
            for (int i = 0; i < 2; i++) {
                const int idx = tid + i*256, r = idx >> 2, kq = (idx & 3)*4;
                pb[i] = (bn + r < N) ? *(const float4*)(W + (size_t)(bn + r)*K + k0 + TBK + kq)
                                     : make_float4(0.f,0.f,0.f,0.f);
            }
        }

        #pragma unroll
        for (int ks = 0; ks < 2; ks++) {
            const int kb = ks*8 + ql;
            uint32_t ahi[MT][4], alo[MT][4], bhi[4][2], blo[4][2];
            #pragma unroll
            for (int mt = 0; mt < MT; mt++) {
                const int r0 = warp_m*(TM/2) + mt*16 + quad;
                ahi[mt][0] = __float_as_uint(AsH[ r0     *APITCH + kb    ]);
                ahi[mt][1] = __float_as_uint(AsH[(r0 + 8)*APITCH + kb    ]);
                ahi[mt][2] = __float_as_uint(AsH[ r0     *APITCH + kb + 4]);
                ahi[mt][3] = __float_as_uint(AsH[(r0 + 8)*APITCH + kb + 4]);
                alo[mt][0] = __float_as_uint(AsL[ r0     *APITCH + kb    ]);
                alo[mt][1] = __float_as_uint(AsL[(r0 + 8)*APITCH + kb    ]);
                alo[mt][2] = __float_as_uint(AsL[ r0     *APITCH + kb + 4]);
                alo[mt][3] = __float_as_uint(AsL[(r0 + 8)*APITCH + kb + 4]);
            }
            #pragma unroll
            for (int nt = 0; nt < 4; nt++) {
                const int c0 = warp_n*32 + nt*8 + quad;
                bhi[nt][0] = __float_as_uint(BsH[c0*APITCH + kb    ]);
                bhi[nt][1] = __float_as_uint(BsH[c0*APITCH + kb + 4]);
                blo[nt][0] = __float_as_uint(BsL[c0*APITCH + kb    ]);
                blo[nt][1] = __float_as_uint(BsL[c0*APITCH + kb + 4]);
            }
            #pragma unroll
            for (int mt = 0; mt < MT; mt++)
                #pragma unroll
                for (int nt = 0; nt < 4; nt++) {
                    mma_tf32(acc[mt][nt], ahi[mt], blo[nt]);
                    mma_tf32(acc[mt][nt], alo[mt], bhi[nt]);
                    mma_tf32(acc[mt][nt], ahi[mt], bhi[nt]);
                }
        }
        __syncthreads();
    }

    // epilogue (M multiple of TM; guard N only)
    #pragma unroll
    for (int mt = 0; mt < MT; mt++) {
        const int r0 = bm + warp_m*(TM/2) + mt*16 + quad;
        #pragma unroll
        for (int nt = 0; nt < 4; nt++) {
            const int cb = bn + warp_n*32 + nt*8 + 2*ql;
            if (cb >= N) continue;
            float v[4] = {acc[mt][nt][0], acc[mt][nt][1], acc[mt][nt][2], acc[mt][nt][3]};
            if (mode == EPI_BIAS || mode == EPI_BIAS_RELU || mode == EPI_BIAS_SOFTPLUS) {
                const float b0 = bias[cb], b1 = bias[cb+1];
                v[0] += b0; v[1] += b1; v[2] += b0; v[3] += b1;
                if (mode == EPI_BIAS_RELU) {
                    #pragma unroll
                    for (int q = 0; q < 4; q++) v[q] = fmaxf(v[q], 0.f);
                } else if (mode == EPI_BIAS_SOFTPLUS) {
                    #pragma unroll
                    for (int q = 0; q < 4; q++)
                        v[q] = (v[q] > 20.f) ? v[q] : log1pf(expf(v[q]));
                }
            } else if (mode == EPI_RES) {
                const float2 r0v = *(const float2*)(res + (size_t)r0*ldc + cb);
                const float2 r1v = *(const float2*)(res + (size_t)(r0+8)*ldc + cb);
                v[0] += r0v.x; v[1] += r0v.y; v[2] += r1v.x; v[3] += r1v.y;
            }
            *(float2*)(C + (size_t)r0*ldc + cb)     = make_float2(v[0], v[1]);
            *(float2*)(C + (size_t)(r0+8)*ldc + cb) = make_float2(v[2], v[3]);
        }
    }
}

#define SMEM128 ((128 + 128) * APITCH * 4 * 2)   // 57344 B
#define SMEM64  ((64  + 128) * APITCH * 4 * 2)   // 43008 B

// ---------------- embedding ----------------
__global__ void embed_kernel(const int* __restrict__ seq,
                             const float* __restrict__ be,
                             const float* __restrict__ pe,
                             float* __restrict__ xe)
{
    const int idx = blockIdx.x * blockDim.x + threadIdx.x;
    const int e   = idx & (EMB-1);
    const int row = idx >> 8;
    const int t   = row & (SEQ-1);
    const int by  = seq[row];
    xe[idx] = be[by*EMB + e] + pe[t*EMB + e];
}

// ---------------- layernorm over D=512 ----------------
__global__ void ln_kernel(const float* __restrict__ x,
                          const float* __restrict__ g,
                          const float* __restrict__ b,
                          float* __restrict__ out)
{
    const int row = blockIdx.x;
    const int tid = threadIdx.x;     // 128
    const float4 v = ((const float4*)(x + (size_t)row*DMODEL))[tid];
    float s  = v.x + v.y + v.z + v.w;
    float ss = v.x*v.x + v.y*v.y + v.z*v.z + v.w*v.w;
    #pragma unroll
    for (int o = 16; o; o >>= 1) {
        s  += __shfl_xor_sync(0xffffffffu, s,  o);
        ss += __shfl_xor_sync(0xffffffffu, ss, o);
    }
    __shared__ float sh_s[4], sh_ss[4];
    const int wid = tid >> 5, lane = tid & 31;
    if (lane == 0) { sh_s[wid] = s; sh_ss[wid] = ss; }
    __syncthreads();
    s  = sh_s[0] + sh_s[1] + sh_s[2] + sh_s[3];
    ss = sh_ss[0] + sh_ss[1] + sh_ss[2] + sh_ss[3];
    const float mu  = s * (1.f/DMODEL);
    const float inv = rsqrtf(ss * (1.f/DMODEL) - mu*mu + 1e-5f);
    const float4 gv = ((const float4*)g)[tid];
    const float4 bv = ((const float4*)b)[tid];
    float4 o4;
    o4.x = (v.x - mu)*inv*gv.x + bv.x;
    o4.y = (v.y - mu)*inv*gv.y + bv.y;
    o4.z = (v.z - mu)*inv*gv.z + bv.z;
    o4.w = (v.w - mu)*inv*gv.w + bv.w;
    ((float4*)(out + (size_t)row*DMODEL))[tid] = o4;
}

// ---------------- causal depthwise conv (DC=4) + bias + SiLU ----------------
__global__ void conv_silu_kernel(const float* __restrict__ xr,
                                 const float* __restrict__ cw,
                                 const float* __restrict__ cb,
                                 float* __restrict__ xs)
{
    const int idx = blockIdx.x * blockDim.x + threadIdx.x;
    const int d   = idx & (DIN-1);
    const int row = idx >> 10;
    const int t   = row & (SEQ-1);
    float acc = cb[d];
    #pragma unroll
    for (int k = 0; k < DCONV; k++) {
        const int tt = t - (DCONV-1) + k;
        if (tt >= 0)
            acc = fmaf(cw[d*DCONV + k],
                       xr[((size_t)(row - (DCONV-1) + k))*(2*DIN) + d], acc);
    }
    xs[idx] = acc / (1.f + __expf(-acc));
}

// ===================== chunked parallel selective scan =====================
__global__ __launch_bounds__(256)
void scan_pass1(const float* __restrict__ xdbl,
                const float* __restrict__ dlt,
                const float* __restrict__ xs,
                const float* __restrict__ A_log)
{
    __shared__ float sB[32][DSTATE];
    const int b    = blockIdx.z;
    const int ch   = blockIdx.y;
    const int warp = threadIdx.x >> 5;
    const int lane = threadIdx.x & 31;
    const int di   = blockIdx.x * 8 + warp;
    const float a0 = -__expf(A_log[di*DSTATE + lane]);
    const float a1 = -__expf(A_log[di*DSTATE + lane + 32]);
    float h0 = 0.f, h1 = 0.f, sd = 0.f;
    const size_t base = (size_t)b*SEQ + (size_t)ch*CLEN;

    for (int t0 = 0; t0 < CLEN; t0 += 32) {
        __syncthreads();
        for (int i = threadIdx.x; i < 32*DSTATE; i += 256) {
            const int r = i >> 6, c = i & 63;
            sB[r][c] = xdbl[(base + t0 + r)*XPN + DRANK + c];
        }
        __syncthreads();
        #pragma unroll 4
        for (int r = 0; r < 32; r++) {
            const size_t row = base + t0 + r;
            const float d_t = dlt[row*DIN + di];
            const float x_t = xs [row*DIN + di];
            const float bx  = d_t * x_t;
            sd += d_t;
            h0 = fmaf(__expf(d_t * a0), h0, bx * sB[r][lane]);
            h1 = fmaf(__expf(d_t * a1), h1, bx * sB[r][lane + 32]);
        }
    }
    const size_t o = (((size_t)b*DIN + di)*NCH + ch)*DSTATE;
    g_hchk[o + lane]      = h0;
    g_hchk[o + lane + 32] = h1;
    if (lane == 0) g_sumd[((size_t)b*DIN + di)*NCH + ch] = sd;
}

__global__ __launch_bounds__(256)
void scan_mid(const float* __restrict__ A_log)
{
    const int b    = blockIdx.z;
    const int warp = threadIdx.x >> 5;
    const int lane = threadIdx.x & 31;
    const int di   = blockIdx.x * 8 + warp;
    const float a0 = -__expf(A_log[di*DSTATE + lane]);
    const float a1 = -__expf(A_log[di*DSTATE + lane + 32]);
    float H0 = 0.f, H1 = 0.f;
    const size_t bd = (size_t)b*DIN + di;
    #pragma unroll
    for (int c = 0; c < NCH; c++) {
        const size_t o = (bd*NCH + c)*DSTATE;
        g_hstart[o + lane]      = H0;
        g_hstart[o + lane + 32] = H1;
        const float sd = g_sumd[bd*NCH + c];
        H0 = fmaf(__expf(sd * a0), H0, g_hchk[o + lane]);
        H1 = fmaf(__expf(sd * a1), H1, g_hchk[o + lane + 32]);
    }
}

__global__ __launch_bounds__(256)
void scan_pass3(const float* __restrict__ xdbl,
                const float* __restrict__ dlt,
                const float* __restrict__ xs,
                const float* __restrict__ xr,
                const float* __restrict__ A_log,
                const float* __restrict__ Dp,
                float* __restrict__ y)
{
    __shared__ float sBC[32][2*DSTATE];
    const int b    = blockIdx.z;
    const int ch   = blockIdx.y;
    const int warp = threadIdx.x >> 5;
    const int lane = threadIdx.x & 31;
    const int di   = blockIdx.x * 8 + warp;
    const float a0 = -__expf(A_log[di*DSTATE + lane]);
    const float a1 = -__expf(A_log[di*DSTATE + lane + 32]);
    const float dp = Dp[di];
    const size_t o = (((size_t)b*DIN + di)*NCH + ch)*DSTATE;
    float h0 = g_hstart[o + lane];
    float h1 = g_hstart[o + lane + 32];
    const size_t base = (size_t)b*SEQ + (size_t)ch*CLEN;

    for (int t0 = 0; t0 < CLEN; t0 += 32) {
        __syncthreads();
        for (int i = threadIdx.x; i < 32*2*DSTATE; i += 256) {
            const int r = i >> 7, c = i & 127;
            sBC[r][c] = xdbl[(base + t0 + r)*XPN + DRANK + c];
        }
        __syncthreads();
        for (int r = 0; r < 32; r++) {
            const size_t row = base + t0 + r;
            const float d_t = dlt[row*DIN + di];
            const float x_t = xs [row*DIN + di];
            const float bx  = d_t * x_t;
            h0 = fmaf(__expf(d_t * a0), h0, bx * sBC[r][lane]);
            h1 = fmaf(__expf(d_t * a1), h1, bx * sBC[r][lane + 32]);
            float yv = h0 * sBC[r][64 + lane] + h1 * sBC[r][96 + lane];
            #pragma unroll
            for (int off = 16; off; off >>= 1)
                yv += __shfl_xor_sync(0xffffffffu, yv, off);
            if (lane == 0) {
                const float r2 = xr[row*(2*DIN) + DIN + di];
                y[row*DIN + di] = (yv + x_t * dp) * (r2 / (1.f + __expf(-r2)));
            }
        }
    }
}

// ---------------- final tiny head ----------------
#define H3R 64
__global__ __launch_bounds__(320)
void head3_kernel(const float* __restrict__ hd2,
                  const float* __restrict__ w,
                  const float* __restrict__ b,
                  float* __restrict__ out)
{
    __shared__ float sh[H3R*132];
    __shared__ float sw[NCLS*130];
    const int tid  = threadIdx.x;
    const int base = blockIdx.x * H3R;
    for (int i = tid; i < H3R*128; i += 320) {
        const int m = i >> 7, j = i & 127;
        sh[m*132 + j] = hd2[(size_t)(base + m)*128 + j];
    }
    for (int i = tid; i < NCLS*128; i += 320) {
        const int c = i >> 7, j = i & 127;
        sw[c*130 + j] = w[c*128 + j];
    }
    __syncthreads();
    const int m = tid / NCLS;
    const int c = tid - m*NCLS;
    float acc = b[c];
    #pragma unroll 8
    for (int j = 0; j < 128; j++)
        acc = fmaf(sh[m*132 + j], sw[c*130 + j], acc);
    out[(size_t)(base + m)*NCLS + c] = acc;
}

// ---------------- host orchestration ----------------
extern "C" void kernel_launch(void* const* d_in, const int* in_sizes, int n_in,
                              void* d_out, int out_size)
{
    (void)in_sizes; (void)n_in; (void)out_size;
    const int*   seq    = (const int*)  d_in[0];
    const float* be     = (const float*)d_in[1];
    const float* pe     = (const float*)d_in[2];
    const float* in_w   = (const float*)d_in[3];
    const float* in_b   = (const float*)d_in[4];
    const float* ln_g   = (const float*)d_in[5];
    const float* ln_b   = (const float*)d_in[6];
    const float* m_in_w = (const float*)d_in[7];
    const float* conv_w = (const float*)d_in[8];
    const float* conv_b = (const float*)d_in[9];
    const float* xp_w   = (const float*)d_in[10];
    const float* dt_w   = (const float*)d_in[11];
    const float* dt_b   = (const float*)d_in[12];
    const float* A_log  = (const float*)d_in[13];
    const float* Dp     = (const float*)d_in[14];
    const float* m_out_w= (const float*)d_in[15];
    const float* h1_w   = (const float*)d_in[16];
    const float* h1_b   = (const float*)d_in[17];
    const float* h2_w   = (const float*)d_in[18];
    const float* h2_b   = (const float*)d_in[19];
    const float* h3_w   = (const float*)d_in[20];
    const float* h3_b   = (const float*)d_in[21];
    float* out = (float*)d_out;

    static bool attr_done = false;
    if (!attr_done) {
        cudaFuncSetAttribute(gemm_tc<128>, cudaFuncAttributeMaxDynamicSharedMemorySize, SMEM128);
        cudaFuncSetAttribute(gemm_tc<64>,  cudaFuncAttributeMaxDynamicSharedMemorySize, SMEM64);
        attr_done = true;
    }

    float *xe,*x,*h,*xr,*xs,*xdbl,*dlt,*y,*hd1,*hd2;
    cudaGetSymbolAddress((void**)&xe,   g_xe);
    cudaGetSymbolAddress((void**)&x,    g_x);
    cudaGetSymbolAddress((void**)&h,    g_h);
    cudaGetSymbolAddress((void**)&xr,   g_xr);
    cudaGetSymbolAddress((void**)&xs,   g_xs);
    cudaGetSymbolAddress((void**)&xdbl, g_xdbl);
    cudaGetSymbolAddress((void**)&dlt,  g_dlt);
    cudaGetSymbolAddress((void**)&y,    g_y);
    cudaGetSymbolAddress((void**)&hd1,  g_hd1);
    cudaGetSymbolAddress((void**)&hd2,  g_hd2);

    embed_kernel<<<MROWS*EMB/256, 256>>>(seq, be, pe, xe);
    gemm_tc<64><<<dim3(DMODEL/TBN, MROWS/64), 256, SMEM64>>>(
        xe, EMB, in_w, x, DMODEL, MROWS, DMODEL, EMB, in_b, nullptr, EPI_BIAS);

    for (int i = 0; i < NLAYER; i++) {
        ln_kernel<<<MROWS, 128>>>(x, ln_g + (size_t)i*DMODEL, ln_b + (size_t)i*DMODEL, h);
        gemm_tc<128><<<dim3(2*DIN/TBN, MROWS/128), 256, SMEM128>>>(
            h, DMODEL, m_in_w + (size_t)i*2*DIN*DMODEL, xr, 2*DIN,
            MROWS, 2*DIN, DMODEL, nullptr, nullptr, EPI_NONE);
        conv_silu_kernel<<<MROWS*DIN/256, 256>>>(
            xr, conv_w + (size_t)i*DIN*DCONV, conv_b + (size_t)i*DIN, xs);
        gemm_tc<64><<<dim3((XPN+TBN-1)/TBN, MROWS/64), 256, SMEM64>>>(
            xs, DIN, xp_w + (size_t)i*XPN*DIN, xdbl, XPN,
            MROWS, XPN, DIN, nullptr, nullptr, EPI_NONE);
        gemm_tc<64><<<dim3(DIN/TBN, MROWS/64), 256, SMEM64>>>(
            xdbl, XPN, dt_w + (size_t)i*DIN*DRANK, dlt, DIN,
            MROWS, DIN, DRANK, dt_b + (size_t)i*DIN, nullptr, EPI_BIAS_SOFTPLUS);
        scan_pass1<<<dim3(DIN/8, NCH, BATCH), 256>>>(
            xdbl, dlt, xs, A_log + (size_t)i*DIN*DSTATE);
        scan_mid<<<dim3(DIN/8, 1, BATCH), 256>>>(A_log + (size_t)i*DIN*DSTATE);
        scan_pass3<<<dim3(DIN/8, NCH, BATCH), 256>>>(
            xdbl, dlt, xs, xr, A_log + (size_t)i*DIN*DSTATE, Dp + (size_t)i*DIN, y);
        gemm_tc<64><<<dim3(DMODEL/TBN, MROWS/64), 256, SMEM64>>>(
            y, DIN, m_out_w + (size_t)i*DMODEL*DIN, x, DMODEL,
            MROWS, DMODEL, DIN, nullptr, x, EPI_RES);
    }

    gemm_tc<64><<<dim3(256/TBN, MROWS/64), 256, SMEM64>>>(
        x, DMODEL, h1_w, hd1, 256, MROWS, 256, DMODEL, h1_b, nullptr, EPI_BIAS_RELU);
    gemm_tc<64><<<dim3(1, MROWS/64), 256, SMEM64>>>(
        hd1, 256, h2_w, hd2, 128, MROWS, 128, 256, h2_b, nullptr, EPI_BIAS_RELU);
    head3_kernel<<<MROWS/H3R, 320>>>(hd2, h3_w, h3_b, out);
}

// round 5
// speedup vs baseline: 2.7208x; 1.1882x over previous
#include <cuda_runtime.h>
#include <cuda_bf16.h>
#include <math.h>
#include <stdint.h>

// ---------------- problem constants ----------------
#define BATCH  2
#define SEQ    2048
#define EMB    256
#define DMODEL 512
#define NLAYER 4
#define DIN    1024
#define DSTATE 64
#define DRANK  32
#define DCONV  4
#define NCLS   5
#define XPN    (DRANK + 2*DSTATE)   // 160
#define MROWS  (BATCH*SEQ)          // 4096
#define NCH    8
#define CLEN   (SEQ/NCH)            // 256

// ---------------- scratch ----------------
__device__ float g_xe  [MROWS*EMB];
__device__ float g_x   [MROWS*DMODEL];
__device__ float g_h   [MROWS*DMODEL];
__device__ float g_xr  [MROWS*2*DIN];
__device__ float g_xs  [MROWS*DIN];
__device__ float g_xdbl[MROWS*XPN];
__device__ float g_dlt [MROWS*DIN];
__device__ float g_y   [MROWS*DIN];
__device__ float g_hd1 [MROWS*256];
__device__ float g_hd2 [MROWS*128];
__device__ float g_hchk  [BATCH*DIN*NCH*DSTATE];
__device__ float g_sumd  [BATCH*DIN*NCH];
__device__ float g_hstart[BATCH*DIN*NCH*DSTATE];

enum { EPI_NONE=0, EPI_BIAS=1, EPI_BIAS_RELU=2, EPI_BIAS_SOFTPLUS=3, EPI_RES=4 };

// ===================== bf16x3 tensor-core GEMM =====================
// C[M,N] = A[M,K] @ W[N,K]^T. fp32 in/out. Each fp32 value split hi+lo bf16
// (staged once into SMEM); inner product = hi*hi + hi*lo + lo*hi via
// mma.m16n8k16.bf16 (2x MACs/instr vs tf32). Double-buffered smem stages,
// one __syncthreads per k-iter. 8 warps (2 x 4), warp tile (TM/2) x 32.
#define TBN 128
#define TBK 16
#define UPITCH 12   // u32 pitch/row: 8 data (16 bf16) + 4 pad -> conflict-free

__device__ __forceinline__ void split_bf4(float4 v, uint2& hi, uint2& lo) {
    __nv_bfloat162 h0 = __floats2bfloat162_rn(v.x, v.y);
    __nv_bfloat162 h1 = __floats2bfloat162_rn(v.z, v.w);
    __nv_bfloat162 l0 = __floats2bfloat162_rn(v.x - __bfloat162float(h0.x),
                                              v.y - __bfloat162float(h0.y));
    __nv_bfloat162 l1 = __floats2bfloat162_rn(v.z - __bfloat162float(h1.x),
                                              v.w - __bfloat162float(h1.y));
    hi = make_uint2(*(uint32_t*)&h0, *(uint32_t*)&h1);
    lo = make_uint2(*(uint32_t*)&l0, *(uint32_t*)&l1);
}
__device__ __forceinline__ void mma_bf16(float* c, const uint32_t* a, const uint32_t* b) {
    asm volatile(
        "mma.sync.aligned.m16n8k16.row.col.f32.bf16.bf16.f32 "
        "{%0,%1,%2,%3}, {%4,%5,%6,%7}, {%8,%9}, {%0,%1,%2,%3};"
        : "+f"(c[0]), "+f"(c[1]), "+f"(c[2]), "+f"(c[3])
        : "r"(a[0]), "r"(a[1]), "r"(a[2]), "r"(a[3]), "r"(b[0]), "r"(b[1]));
}

template<int TM>
__global__ __launch_bounds__(256)
void gemm_bf(const float* __restrict__ A, int lda,
             const float* __restrict__ W,            // [N,K] row-major
             float* __restrict__ C, int ldc,
             int M, int N, int K,
             const float* __restrict__ bias,
             const float* __restrict__ res,
             int mode)
{
    constexpr int MT  = TM / 32;          // m16 tiles per warp
    constexpr int AIT = TM / 64;          // float4 A loads per thread
    constexpr int ASZ = TM  * UPITCH;     // u32 per A plane
    constexpr int BSZ = TBN * UPITCH;     // u32 per B plane
    constexpr int STG = 2*ASZ + 2*BSZ;    // u32 per stage (AsH,AsL,BsH,BsL)

    extern __shared__ uint32_t sm[];

    const int tid    = threadIdx.x;
    const int lane   = tid & 31;
    const int wid    = tid >> 5;
    const int warp_m = wid >> 2;
    const int warp_n = wid & 3;
    const int quad   = lane >> 2;
    const int ql     = lane & 3;
    const int bm     = blockIdx.y * TM;
    const int bn     = blockIdx.x * TBN;

    float acc[MT][4][4];
    #pragma unroll
    for (int i = 0; i < MT; i++)
        #pragma unroll
        for (int j = 0; j < 4; j++)
            #pragma unroll
            for (int k = 0; k < 4; k++) acc[i][j][k] = 0.f;

    float4 pa[AIT], pb[2];

    // gmem tile -> regs
    auto load_tile = [&](int k0) {
        #pragma unroll
        for (int i = 0; i < AIT; i++) {
            const int idx = tid + i*256, r = idx >> 2, kq = (idx & 3)*4;
            pa[i] = *(const float4*)(A + (size_t)(bm + r)*lda + k0 + kq);
        }
        #pragma unroll
        for (int i = 0; i < 2; i++) {
            const int idx = tid + i*256, r = idx >> 2, kq = (idx & 3)*4;
            pb[i] = (bn + r < N) ? *(const float4*)(W + (size_t)(bn + r)*K + k0 + kq)
                                 : make_float4(0.f,0.f,0.f,0.f);
        }
    };
    // regs -> smem stage s with hi/lo split
    auto store_tile = [&](int s) {
        uint32_t* AsH = sm + s*STG;
        uint32_t* AsL = AsH + ASZ;
        uint32_t* BsH = AsL + ASZ;
        uint32_t* BsL = BsH + BSZ;
        #pragma unroll
        for (int i = 0; i < AIT; i++) {
            const int idx = tid + i*256, r = idx >> 2, ko = (idx & 3)*2;
            uint2 hi, lo; split_bf4(pa[i], hi, lo);
            *(uint2*)(&AsH[r*UPITCH + ko]) = hi;
            *(uint2*)(&AsL[r*UPITCH + ko]) = lo;
        }
        #pragma unroll
        for (int i = 0; i < 2; i++) {
            const int idx = tid + i*256, r = idx >> 2, ko = (idx & 3)*2;
            uint2 hi, lo; split_bf4(pb[i], hi, lo);
            *(uint2*)(&BsH[r*UPITCH + ko]) = hi;
            *(uint2*)(&BsL[r*UPITCH + ko]) = lo;
        }
    };

    load_tile(0);
    store_tile(0);
    __syncthreads();

    int cur = 0;
    for (int k0 = 0; k0 < K; k0 += TBK) {
        const bool has_next = (k0 + TBK < K);
        if (has_next) load_tile(k0 + TBK);

        const uint32_t* AsH = sm + cur*STG;
        const uint32_t* AsL = AsH + ASZ;
        const uint32_t* BsH = AsL + ASZ;
        const uint32_t* BsL = BsH + BSZ;

        uint32_t ahi[MT][4], alo[MT][4], bhi[4][2], blo[4][2];
        #pragma unroll
        for (int mt = 0; mt < MT; mt++) {
            const int r0 = warp_m*(TM/2) + mt*16 + quad;
            ahi[mt][0] = AsH[ r0     *UPITCH + ql    ];
            ahi[mt][1] = AsH[(r0 + 8)*UPITCH + ql    ];
            ahi[mt][2] = AsH[ r0     *UPITCH + 4 + ql];
            ahi[mt][3] = AsH[(r0 + 8)*UPITCH + 4 + ql];
            alo[mt][0] = AsL[ r0     *UPITCH + ql    ];
            alo[mt][1] = AsL[(r0 + 8)*UPITCH + ql    ];
            alo[mt][2] = AsL[ r0     *UPITCH + 4 + ql];
            alo[mt][3] = AsL[(r0 + 8)*UPITCH + 4 + ql];
        }
        #pragma unroll
        for (int nt = 0; nt < 4; nt++) {
            const int c0 = warp_n*32 + nt*8 + quad;
            bhi[nt][0] = BsH[c0*UPITCH + ql    ];
            bhi[nt][1] = BsH[c0*UPITCH + 4 + ql];
            blo[nt][0] = BsL[c0*UPITCH + ql    ];
            blo[nt][1] = BsL[c0*UPITCH + 4 + ql];
        }
        #pragma unroll
        for (int mt = 0; mt < MT; mt++)
            #pragma unroll
            for (int nt = 0; nt < 4; nt++) {
                mma_bf16(acc[mt][nt], ahi[mt], blo[nt]);
                mma_bf16(acc[mt][nt], alo[mt], bhi[nt]);
                mma_bf16(acc[mt][nt], ahi[mt], bhi[nt]);
            }

        if (has_next) store_tile(1 - cur);
        __syncthreads();
        cur ^= 1;
    }

    // epilogue (M multiple of TM; guard N only)
    #pragma unroll
    for (int mt = 0; mt < MT; mt++) {
        const int r0 = bm + warp_m*(TM/2) + mt*16 + quad;
        #pragma unroll
        for (int nt = 0; nt < 4; nt++) {
            const int cb = bn + warp_n*32 + nt*8 + 2*ql;
            if (cb >= N) continue;
            float v[4] = {acc[mt][nt][0], acc[mt][nt][1], acc[mt][nt][2], acc[mt][nt][3]};
            if (mode == EPI_BIAS || mode == EPI_BIAS_RELU || mode == EPI_BIAS_SOFTPLUS) {
                const float b0 = bias[cb], b1 = bias[cb+1];
                v[0] += b0; v[1] += b1; v[2] += b0; v[3] += b1;
                if (mode == EPI_BIAS_RELU) {
                    #pragma unroll
                    for (int q = 0; q < 4; q++) v[q] = fmaxf(v[q], 0.f);
                } else if (mode == EPI_BIAS_SOFTPLUS) {
                    #pragma unroll
                    for (int q = 0; q < 4; q++)
                        v[q] = (v[q] > 20.f) ? v[q] : log1pf(expf(v[q]));
                }
            } else if (mode == EPI_RES) {
                const float2 r0v = *(const float2*)(res + (size_t)r0*ldc + cb);
                const float2 r1v = *(const float2*)(res + (size_t)(r0+8)*ldc + cb);
                v[0] += r0v.x; v[1] += r0v.y; v[2] += r1v.x; v[3] += r1v.y;
            }
            *(float2*)(C + (size_t)r0*ldc + cb)     = make_float2(v[0], v[1]);
            *(float2*)(C + (size_t)(r0+8)*ldc + cb) = make_float2(v[2], v[3]);
        }
    }
}

#define SMEM128 (2 * (2*128*UPITCH + 2*128*UPITCH) * 4)   // 49152 B
#define SMEM64  (2 * (2*64 *UPITCH + 2*128*UPITCH) * 4)   // 36864 B

// ---------------- embedding ----------------
__global__ void embed_kernel(const int* __restrict__ seq,
                             const float* __restrict__ be,
                             const float* __restrict__ pe,
                             float* __restrict__ xe)
{
    const int idx = blockIdx.x * blockDim.x + threadIdx.x;
    const int e   = idx & (EMB-1);
    const int row = idx >> 8;
    const int t   = row & (SEQ-1);
    const int by  = seq[row];
    xe[idx] = be[by*EMB + e] + pe[t*EMB + e];
}

// ---------------- layernorm over D=512 ----------------
__global__ void ln_kernel(const float* __restrict__ x,
                          const float* __restrict__ g,
                          const float* __restrict__ b,
                          float* __restrict__ out)
{
    const int row = blockIdx.x;
    const int tid = threadIdx.x;     // 128
    const float4 v = ((const float4*)(x + (size_t)row*DMODEL))[tid];
    float s  = v.x + v.y + v.z + v.w;
    float ss = v.x*v.x + v.y*v.y + v.z*v.z + v.w*v.w;
    #pragma unroll
    for (int o = 16; o; o >>= 1) {
        s  += __shfl_xor_sync(0xffffffffu, s,  o);
        ss += __shfl_xor_sync(0xffffffffu, ss, o);
    }
    __shared__ float sh_s[4], sh_ss[4];
    const int wid = tid >> 5, lane = tid & 31;
    if (lane == 0) { sh_s[wid] = s; sh_ss[wid] = ss; }
    __syncthreads();
    s  = sh_s[0] + sh_s[1] + sh_s[2] + sh_s[3];
    ss = sh_ss[0] + sh_ss[1] + sh_ss[2] + sh_ss[3];
    const float mu  = s * (1.f/DMODEL);
    const float inv = rsqrtf(ss * (1.f/DMODEL) - mu*mu + 1e-5f);
    const float4 gv = ((const float4*)g)[tid];
    const float4 bv = ((const float4*)b)[tid];
    float4 o4;
    o4.x = (v.x - mu)*inv*gv.x + bv.x;
    o4.y = (v.y - mu)*inv*gv.y + bv.y;
    o4.z = (v.z - mu)*inv*gv.z + bv.z;
    o4.w = (v.w - mu)*inv*gv.w + bv.w;
    ((float4*)(out + (size_t)row*DMODEL))[tid] = o4;
}

// ---------------- causal depthwise conv (DC=4) + bias + SiLU ----------------
__global__ void conv_silu_kernel(const float* __restrict__ xr,
                                 const float* __restrict__ cw,
                                 const float* __restrict__ cb,
                                 float* __restrict__ xs)
{
    const int idx = blockIdx.x * blockDim.x + threadIdx.x;
    const int d   = idx & (DIN-1);
    const int row = idx >> 10;
    const int t   = row & (SEQ-1);
    float acc = cb[d];
    #pragma unroll
    for (int k = 0; k < DCONV; k++) {
        const int tt = t - (DCONV-1) + k;
        if (tt >= 0)
            acc = fmaf(cw[d*DCONV + k],
                       xr[((size_t)(row - (DCONV-1) + k))*(2*DIN) + d], acc);
    }
    xs[idx] = acc / (1.f + __expf(-acc));
}

// ===================== chunked parallel selective scan =====================
__global__ __launch_bounds__(256)
void scan_pass1(const float* __restrict__ xdbl,
                const float* __restrict__ dlt,
                const float* __restrict__ xs,
                const float* __restrict__ A_log)
{
    __shared__ float sB[32][DSTATE];
    const int b    = blockIdx.z;
    const int ch   = blockIdx.y;
    const int warp = threadIdx.x >> 5;
    const int lane = threadIdx.x & 31;
    const int di   = blockIdx.x * 8 + warp;
    const float a0 = -__expf(A_log[di*DSTATE + lane]);
    const float a1 = -__expf(A_log[di*DSTATE + lane + 32]);
    float h0 = 0.f, h1 = 0.f, sd = 0.f;
    const size_t base = (size_t)b*SEQ + (size_t)ch*CLEN;

    for (int t0 = 0; t0 < CLEN; t0 += 32) {
        __syncthreads();
        for (int i = threadIdx.x; i < 32*DSTATE; i += 256) {
            const int r = i >> 6, c = i & 63;
            sB[r][c] = xdbl[(base + t0 + r)*XPN + DRANK + c];
        }
        __syncthreads();
        #pragma unroll 4
        for (int r = 0; r < 32; r++) {
            const size_t row = base + t0 + r;
            const float d_t = dlt[row*DIN + di];
            const float x_t = xs [row*DIN + di];
            const float bx  = d_t * x_t;
            sd += d_t;
            h0 = fmaf(__expf(d_t * a0), h0, bx * sB[r][lane]);
            h1 = fmaf(__expf(d_t * a1), h1, bx * sB[r][lane + 32]);
        }
    }
    const size_t o = (((size_t)b*DIN + di)*NCH + ch)*DSTATE;
    g_hchk[o + lane]      = h0;
    g_hchk[o + lane + 32] = h1;
    if (lane == 0) g_sumd[((size_t)b*DIN + di)*NCH + ch] = sd;
}

__global__ __launch_bounds__(256)
void scan_mid(const float* __restrict__ A_log)
{
    const int b    = blockIdx.z;
    const int warp = threadIdx.x >> 5;
    const int lane = threadIdx.x & 31;
    const int di   = blockIdx.x * 8 + warp;
    const float a0 = -__expf(A_log[di*DSTATE + lane]);
    const float a1 = -__expf(A_log[di*DSTATE + lane + 32]);
    float H0 = 0.f, H1 = 0.f;
    const size_t bd = (size_t)b*DIN + di;
    #pragma unroll
    for (int c = 0; c < NCH; c++) {
        const size_t o = (bd*NCH + c)*DSTATE;
        g_hstart[o + lane]      = H0;
        g_hstart[o + lane + 32] = H1;
        const float sd = g_sumd[bd*NCH + c];
        H0 = fmaf(__expf(sd * a0), H0, g_hchk[o + lane]);
        H1 = fmaf(__expf(sd * a1), H1, g_hchk[o + lane + 32]);
    }
}

__global__ __launch_bounds__(256)
void scan_pass3(const float* __restrict__ xdbl,
                const float* __restrict__ dlt,
                const float* __restrict__ xs,
                const float* __restrict__ xr,
                const float* __restrict__ A_log,
                const float* __restrict__ Dp,
                float* __restrict__ y)
{
    __shared__ float sBC[32][2*DSTATE];
    const int b    = blockIdx.z;
    const int ch   = blockIdx.y;
    const int warp = threadIdx.x >> 5;
    const int lane = threadIdx.x & 31;
    const int di   = blockIdx.x * 8 + warp;
    const float a0 = -__expf(A_log[di*DSTATE + lane]);
    const float a1 = -__expf(A_log[di*DSTATE + lane + 32]);
    const float dp = Dp[di];
    const size_t o = (((size_t)b*DIN + di)*NCH + ch)*DSTATE;
    float h0 = g_hstart[o + lane];
    float h1 = g_hstart[o + lane + 32];
    const size_t base = (size_t)b*SEQ + (size_t)ch*CLEN;

    for (int t0 = 0; t0 < CLEN; t0 += 32) {
        __syncthreads();
        for (int i = threadIdx.x; i < 32*2*DSTATE; i += 256) {
            const int r = i >> 7, c = i & 127;
            sBC[r][c] = xdbl[(base + t0 + r)*XPN + DRANK + c];
        }
        __syncthreads();
        for (int r = 0; r < 32; r++) {
            const size_t row = base + t0 + r;
            const float d_t = dlt[row*DIN + di];
            const float x_t = xs [row*DIN + di];
            const float bx  = d_t * x_t;
            h0 = fmaf(__expf(d_t * a0), h0, bx * sBC[r][lane]);
            h1 = fmaf(__expf(d_t * a1), h1, bx * sBC[r][lane + 32]);
            float yv = h0 * sBC[r][64 + lane] + h1 * sBC[r][96 + lane];
            #pragma unroll
            for (int off = 16; off; off >>= 1)
                yv += __shfl_xor_sync(0xffffffffu, yv, off);
            if (lane == 0) {
                const float r2 = xr[row*(2*DIN) + DIN + di];
                y[row*DIN + di] = (yv + x_t * dp) * (r2 / (1.f + __expf(-r2)));
            }
        }
    }
}

// ---------------- final tiny head ----------------
#define H3R 64
__global__ __launch_bounds__(320)
void head3_kernel(const float* __restrict__ hd2,
                  const float* __restrict__ w,
                  const float* __restrict__ b,
                  float* __restrict__ out)
{
    __shared__ float sh[H3R*132];
    __shared__ float sw[NCLS*130];
    const int tid  = threadIdx.x;
    const int base = blockIdx.x * H3R;
    for (int i = tid; i < H3R*128; i += 320) {
        const int m = i >> 7, j = i & 127;
        sh[m*132 + j] = hd2[(size_t)(base + m)*128 + j];
    }
    for (int i = tid; i < NCLS*128; i += 320) {
        const int c = i >> 7, j = i & 127;
        sw[c*130 + j] = w[c*128 + j];
    }
    __syncthreads();
    const int m = tid / NCLS;
    const int c = tid - m*NCLS;
    float acc = b[c];
    #pragma unroll 8
    for (int j = 0; j < 128; j++)
        acc = fmaf(sh[m*132 + j], sw[c*130 + j], acc);
    out[(size_t)(base + m)*NCLS + c] = acc;
}

// ---------------- host orchestration ----------------
extern "C" void kernel_launch(void* const* d_in, const int* in_sizes, int n_in,
                              void* d_out, int out_size)
{
    (void)in_sizes; (void)n_in; (void)out_size;
    const int*   seq    = (const int*)  d_in[0];
    const float* be     = (const float*)d_in[1];
    const float* pe     = (const float*)d_in[2];
    const float* in_w   = (const float*)d_in[3];
    const float* in_b   = (const float*)d_in[4];
    const float* ln_g   = (const float*)d_in[5];
    const float* ln_b   = (const float*)d_in[6];
    const float* m_in_w = (const float*)d_in[7];
    const float* conv_w = (const float*)d_in[8];
    const float* conv_b = (const float*)d_in[9];
    const float* xp_w   = (const float*)d_in[10];
    const float* dt_w   = (const float*)d_in[11];
    const float* dt_b   = (const float*)d_in[12];
    const float* A_log  = (const float*)d_in[13];
    const float* Dp     = (const float*)d_in[14];
    const float* m_out_w= (const float*)d_in[15];
    const float* h1_w   = (const float*)d_in[16];
    const float* h1_b   = (const float*)d_in[17];
    const float* h2_w   = (const float*)d_in[18];
    const float* h2_b   = (const float*)d_in[19];
    const float* h3_w   = (const float*)d_in[20];
    const float* h3_b   = (const float*)d_in[21];
    float* out = (float*)d_out;

    static bool attr_done = false;
    if (!attr_done) {
        cudaFuncSetAttribute(gemm_bf<128>, cudaFuncAttributeMaxDynamicSharedMemorySize, SMEM128);
        cudaFuncSetAttribute(gemm_bf<64>,  cudaFuncAttributeMaxDynamicSharedMemorySize, SMEM64);
        attr_done = true;
    }

    float *xe,*x,*h,*xr,*xs,*xdbl,*dlt,*y,*hd1,*hd2;
    cudaGetSymbolAddress((void**)&xe,   g_xe);
    cudaGetSymbolAddress((void**)&x,    g_x);
    cudaGetSymbolAddress((void**)&h,    g_h);
    cudaGetSymbolAddress((void**)&xr,   g_xr);
    cudaGetSymbolAddress((void**)&xs,   g_xs);
    cudaGetSymbolAddress((void**)&xdbl, g_xdbl);
    cudaGetSymbolAddress((void**)&dlt,  g_dlt);
    cudaGetSymbolAddress((void**)&y,    g_y);
    cudaGetSymbolAddress((void**)&hd1,  g_hd1);
    cudaGetSymbolAddress((void**)&hd2,  g_hd2);

    embed_kernel<<<MROWS*EMB/256, 256>>>(seq, be, pe, xe);
    gemm_bf<64><<<dim3(DMODEL/TBN, MROWS/64), 256, SMEM64>>>(
        xe, EMB, in_w, x, DMODEL, MROWS, DMODEL, EMB, in_b, nullptr, EPI_BIAS);

    for (int i = 0; i < NLAYER; i++) {
        ln_kernel<<<MROWS, 128>>>(x, ln_g + (size_t)i*DMODEL, ln_b + (size_t)i*DMODEL, h);
        gemm_bf<128><<<dim3(2*DIN/TBN, MROWS/128), 256, SMEM128>>>(
            h, DMODEL, m_in_w + (size_t)i*2*DIN*DMODEL, xr, 2*DIN,
            MROWS, 2*DIN, DMODEL, nullptr, nullptr, EPI_NONE);
        conv_silu_kernel<<<MROWS*DIN/256, 256>>>(
            xr, conv_w + (size_t)i*DIN*DCONV, conv_b + (size_t)i*DIN, xs);
        gemm_bf<64><<<dim3((XPN+TBN-1)/TBN, MROWS/64), 256, SMEM64>>>(
            xs, DIN, xp_w + (size_t)i*XPN*DIN, xdbl, XPN,
            MROWS, XPN, DIN, nullptr, nullptr, EPI_NONE);
        gemm_bf<64><<<dim3(DIN/TBN, MROWS/64), 256, SMEM64>>>(
            xdbl, XPN, dt_w + (size_t)i*DIN*DRANK, dlt, DIN,
            MROWS, DIN, DRANK, dt_b + (size_t)i*DIN, nullptr, EPI_BIAS_SOFTPLUS);
        scan_pass1<<<dim3(DIN/8, NCH, BATCH), 256>>>(
            xdbl, dlt, xs, A_log + (size_t)i*DIN*DSTATE);
        scan_mid<<<dim3(DIN/8, 1, BATCH), 256>>>(A_log + (size_t)i*DIN*DSTATE);
        scan_pass3<<<dim3(DIN/8, NCH, BATCH), 256>>>(
            xdbl, dlt, xs, xr, A_log + (size_t)i*DIN*DSTATE, Dp + (size_t)i*DIN, y);
        gemm_bf<64><<<dim3(DMODEL/TBN, MROWS/64), 256, SMEM64>>>(
            y, DIN, m_out_w + (size_t)i*DMODEL*DIN, x, DMODEL,
            MROWS, DMODEL, DIN, nullptr, x, EPI_RES);
    }

    gemm_bf<64><<<dim3(256/TBN, MROWS/64), 256, SMEM64>>>(
        x, DMODEL, h1_w, hd1, 256, MROWS, 256, DMODEL, h1_b, nullptr, EPI_BIAS_RELU);
    gemm_bf<64><<<dim3(1, MROWS/64), 256, SMEM64>>>(
        hd1, 256, h2_w, hd2, 128, MROWS, 128, 256, h2_b, nullptr, EPI_BIAS_RELU);
    head3_kernel<<<MROWS/H3R, 320>>>(hd2, h3_w, h3_b, out);
}